// round 5
// baseline (speedup 1.0000x reference)
#include <cuda_runtime.h>
#include <cstdint>

#define B      2
#define NNODE  50000
#define IN_DIM 64
#define HID    256
#define OUT    128
#define NEDGE  500000

#define EPB 32           // edges per block (edge mlp v2)
#define MPB 32           // nodes per block (node mlp v2)
#define DPB 16           // nodes per block (decode)
#define RS  36           // smem row stride in floats (pad; multiple of 4 for float4)

// Scratch (allocation-guard-safe __device__ globals)
__device__ float g_H[(size_t)B * NNODE * OUT];   // 51.2 MB accumulator
__device__ int   g_eu[NEDGE];
__device__ int   g_ev[NEDGE];
__device__ int   g_is64;

// ---------------------------------------------------------------------------
// Kernel 0a/0b: edge dtype detect + SoA normalize (unchanged, proven)
// ---------------------------------------------------------------------------
__global__ void detect_edge_dtype_kernel(const int* __restrict__ e32)
{
    if (threadIdx.x == 0 && blockIdx.x == 0) {
        int all_zero = 1;
        #pragma unroll 1
        for (int i = 1; i < 256; i += 2)
            if (e32[i] != 0) { all_zero = 0; break; }
        g_is64 = all_zero;
    }
}

__global__ __launch_bounds__(256) void convert_edges_kernel(const int* __restrict__ e32)
{
    const int e = blockIdx.x * 256 + threadIdx.x;
    if (e < NEDGE) {
        if (g_is64) { g_eu[e] = e32[4 * e + 0]; g_ev[e] = e32[4 * e + 2]; }
        else        { g_eu[e] = e32[2 * e + 0]; g_ev[e] = e32[2 * e + 1]; }
    }
}

// ---------------------------------------------------------------------------
// Kernel 1 (v2): node MLP, register-blocked.
//   GEMM1: xsT[64][MPB] @ nw1[64][256] -> hsT[256][MPB] (relu)
//   GEMM2: hsT @ nw2[256][128] -> g_H (plain stores)
// smem: xsT 64*RS + hsT 256*RS floats = 46.1 KB
// ---------------------------------------------------------------------------
__global__ __launch_bounds__(256, 4) void node_mlp_kernel(
    const float* __restrict__ x,
    const float* __restrict__ nw1, const float* __restrict__ nb1,
    const float* __restrict__ nw2, const float* __restrict__ nb2)
{
    extern __shared__ float sm[];
    float* xsT = sm;                       // [IN_DIM][RS]
    float* hsT = sm + IN_DIM * RS;         // [HID][RS]

    const int t = threadIdx.x;
    const int base = blockIdx.x * MPB;     // flattened node idx in [0, B*N)

    // gather x tile transposed: xsT[c][m] = x[base+m][c]
    #pragma unroll
    for (int i = t; i < MPB * IN_DIM; i += 256) {
        const int m = i >> 6, c = i & (IN_DIM - 1);
        xsT[c * RS + m] = x[(size_t)(base + m) * IN_DIM + c];
    }
    __syncthreads();

    // ---- GEMM1: thread tile 8(m) x 4(n), 4 row-groups x 64 col-groups ----
    {
        const int m0 = (t >> 6) * 8;
        const int n0 = (t & 63) * 4;
        const float4 b1 = *(const float4*)&nb1[n0];
        float acc[8][4];
        #pragma unroll
        for (int i = 0; i < 8; i++) {
            acc[i][0] = b1.x; acc[i][1] = b1.y; acc[i][2] = b1.z; acc[i][3] = b1.w;
        }
        #pragma unroll 4
        for (int k = 0; k < IN_DIM; k++) {
            const float4 bv = *(const float4*)&nw1[k * HID + n0];
            const float4 a0 = *(const float4*)&xsT[k * RS + m0];
            const float4 a1 = *(const float4*)&xsT[k * RS + m0 + 4];
            const float a[8] = {a0.x, a0.y, a0.z, a0.w, a1.x, a1.y, a1.z, a1.w};
            const float bb[4] = {bv.x, bv.y, bv.z, bv.w};
            #pragma unroll
            for (int i = 0; i < 8; i++)
                #pragma unroll
                for (int j = 0; j < 4; j++)
                    acc[i][j] = fmaf(a[i], bb[j], acc[i][j]);
        }
        // relu + transposed write: hsT[n][m]
        #pragma unroll
        for (int j = 0; j < 4; j++) {
            float4 lo = make_float4(fmaxf(acc[0][j], 0.f), fmaxf(acc[1][j], 0.f),
                                    fmaxf(acc[2][j], 0.f), fmaxf(acc[3][j], 0.f));
            float4 hi = make_float4(fmaxf(acc[4][j], 0.f), fmaxf(acc[5][j], 0.f),
                                    fmaxf(acc[6][j], 0.f), fmaxf(acc[7][j], 0.f));
            *(float4*)&hsT[(n0 + j) * RS + m0]     = lo;
            *(float4*)&hsT[(n0 + j) * RS + m0 + 4] = hi;
        }
    }
    __syncthreads();

    // ---- GEMM2: thread tile 4(m) x 4(n), 8 row-groups x 32 col-groups ----
    {
        const int m0 = (t >> 5) * 4;
        const int n0 = (t & 31) * 4;
        const float4 b2 = *(const float4*)&nb2[n0];
        float acc[4][4];
        #pragma unroll
        for (int i = 0; i < 4; i++) {
            acc[i][0] = b2.x; acc[i][1] = b2.y; acc[i][2] = b2.z; acc[i][3] = b2.w;
        }
        #pragma unroll 4
        for (int k = 0; k < HID; k++) {
            const float4 bv = *(const float4*)&nw2[k * OUT + n0];
            const float4 av = *(const float4*)&hsT[k * RS + m0];
            const float a[4] = {av.x, av.y, av.z, av.w};
            const float bb[4] = {bv.x, bv.y, bv.z, bv.w};
            #pragma unroll
            for (int i = 0; i < 4; i++)
                #pragma unroll
                for (int j = 0; j < 4; j++)
                    acc[i][j] = fmaf(a[i], bb[j], acc[i][j]);
        }
        #pragma unroll
        for (int i = 0; i < 4; i++)
            *(float4*)&g_H[(size_t)(base + m0 + i) * OUT + n0] =
                make_float4(acc[i][0], acc[i][1], acc[i][2], acc[i][3]);
    }
}

// ---------------------------------------------------------------------------
// Kernel 2 (v2): edge MLP, register-blocked + atomic scatter.
// smem: esT 128*RS + hsT 256*RS floats + 2*EPB ints = 55.5 KB
// ---------------------------------------------------------------------------
__global__ __launch_bounds__(256, 4) void edge_mlp_kernel(
    const float* __restrict__ x,
    const float* __restrict__ ew1, const float* __restrict__ eb1,
    const float* __restrict__ ew2, const float* __restrict__ eb2)
{
    extern __shared__ float sm[];
    float* esT = sm;                             // [2*IN_DIM][RS]
    float* hsT = sm + 2 * IN_DIM * RS;           // [HID][RS]
    int*   us  = (int*)(sm + (2 * IN_DIM + HID) * RS);
    int*   vs  = us + EPB;

    const int t = threadIdx.x;
    const long long idx = (long long)blockIdx.x * EPB;
    const int b  = (int)(idx / NEDGE);
    const int e0 = (int)(idx % NEDGE);

    if (t < EPB) { us[t] = g_eu[e0 + t]; vs[t] = g_ev[e0 + t]; }
    __syncthreads();

    // gather concat(x[u],x[v]) transposed: esT[c][m]
    const float* xb = x + (size_t)b * NNODE * IN_DIM;
    #pragma unroll
    for (int i = t; i < EPB * 2 * IN_DIM; i += 256) {
        const int m = i >> 7, c = i & 127;
        const int node = (c < IN_DIM) ? us[m] : vs[m];
        esT[c * RS + m] = xb[(size_t)node * IN_DIM + (c & (IN_DIM - 1))];
    }
    __syncthreads();

    // ---- GEMM1: K=128, N=256; thread tile 8x4 ----
    {
        const int m0 = (t >> 6) * 8;
        const int n0 = (t & 63) * 4;
        const float4 b1 = *(const float4*)&eb1[n0];
        float acc[8][4];
        #pragma unroll
        for (int i = 0; i < 8; i++) {
            acc[i][0] = b1.x; acc[i][1] = b1.y; acc[i][2] = b1.z; acc[i][3] = b1.w;
        }
        #pragma unroll 4
        for (int k = 0; k < 2 * IN_DIM; k++) {
            const float4 bv = *(const float4*)&ew1[k * HID + n0];
            const float4 a0 = *(const float4*)&esT[k * RS + m0];
            const float4 a1 = *(const float4*)&esT[k * RS + m0 + 4];
            const float a[8] = {a0.x, a0.y, a0.z, a0.w, a1.x, a1.y, a1.z, a1.w};
            const float bb[4] = {bv.x, bv.y, bv.z, bv.w};
            #pragma unroll
            for (int i = 0; i < 8; i++)
                #pragma unroll
                for (int j = 0; j < 4; j++)
                    acc[i][j] = fmaf(a[i], bb[j], acc[i][j]);
        }
        #pragma unroll
        for (int j = 0; j < 4; j++) {
            float4 lo = make_float4(fmaxf(acc[0][j], 0.f), fmaxf(acc[1][j], 0.f),
                                    fmaxf(acc[2][j], 0.f), fmaxf(acc[3][j], 0.f));
            float4 hi = make_float4(fmaxf(acc[4][j], 0.f), fmaxf(acc[5][j], 0.f),
                                    fmaxf(acc[6][j], 0.f), fmaxf(acc[7][j], 0.f));
            *(float4*)&hsT[(n0 + j) * RS + m0]     = lo;
            *(float4*)&hsT[(n0 + j) * RS + m0 + 4] = hi;
        }
    }
    __syncthreads();

    // ---- GEMM2: K=256, N=128; thread tile 4x4 + scatter ----
    {
        const int m0 = (t >> 5) * 4;
        const int n0 = (t & 31) * 4;
        const float4 b2 = *(const float4*)&eb2[n0];
        float acc[4][4];
        #pragma unroll
        for (int i = 0; i < 4; i++) {
            acc[i][0] = b2.x; acc[i][1] = b2.y; acc[i][2] = b2.z; acc[i][3] = b2.w;
        }
        #pragma unroll 4
        for (int k = 0; k < HID; k++) {
            const float4 bv = *(const float4*)&ew2[k * OUT + n0];
            const float4 av = *(const float4*)&hsT[k * RS + m0];
            const float a[4] = {av.x, av.y, av.z, av.w};
            const float bb[4] = {bv.x, bv.y, bv.z, bv.w};
            #pragma unroll
            for (int i = 0; i < 4; i++)
                #pragma unroll
                for (int j = 0; j < 4; j++)
                    acc[i][j] = fmaf(a[i], bb[j], acc[i][j]);
        }
        float* Hb = g_H + (size_t)b * NNODE * OUT;
        #pragma unroll
        for (int i = 0; i < 4; i++) {
            const int u = us[m0 + i], v = vs[m0 + i];
            #pragma unroll
            for (int j = 0; j < 4; j++) {
                atomicAdd(&Hb[(size_t)u * OUT + n0 + j], acc[i][j]);
                atomicAdd(&Hb[(size_t)v * OUT + n0 + j], acc[i][j]);
            }
        }
    }
}

// ---------------------------------------------------------------------------
// Kernel 3: decode (unchanged, small): out = H @ dw + db
// ---------------------------------------------------------------------------
__global__ __launch_bounds__(256) void decode_kernel(
    const float* __restrict__ dw, const float* __restrict__ db,
    float* __restrict__ out)
{
    __shared__ __align__(16) float hs[DPB][OUT];

    const int base = blockIdx.x * DPB;
    const int t = threadIdx.x;

    for (int i = t; i < DPB * OUT; i += 256)
        hs[i / OUT][i % OUT] = g_H[(size_t)base * OUT + i];
    __syncthreads();

    const int o   = t & (IN_DIM - 1);
    const int nb0 = (t >> 6) * (DPB / 4);
    float acc[DPB / 4];
    {
        const float bb = db[o];
        #pragma unroll
        for (int n = 0; n < DPB / 4; n++) acc[n] = bb;
    }
    #pragma unroll 4
    for (int k = 0; k < OUT; k += 4) {
        const float w0 = dw[(k + 0) * IN_DIM + o];
        const float w1 = dw[(k + 1) * IN_DIM + o];
        const float w2 = dw[(k + 2) * IN_DIM + o];
        const float w3 = dw[(k + 3) * IN_DIM + o];
        #pragma unroll
        for (int n = 0; n < DPB / 4; n++) {
            float4 v = *reinterpret_cast<const float4*>(&hs[nb0 + n][k]);
            acc[n] = fmaf(v.x, w0, acc[n]);
            acc[n] = fmaf(v.y, w1, acc[n]);
            acc[n] = fmaf(v.z, w2, acc[n]);
            acc[n] = fmaf(v.w, w3, acc[n]);
        }
    }
    #pragma unroll
    for (int n = 0; n < DPB / 4; n++)
        out[(size_t)(base + nb0 + n) * IN_DIM + o] = acc[n];
}

// ---------------------------------------------------------------------------
extern "C" void kernel_launch(void* const* d_in, const int* in_sizes, int n_in,
                              void* d_out, int out_size)
{
    const float* x   = (const float*)d_in[0];
    const int*   e32 = (const int*)d_in[1];
    const float* ew1 = (const float*)d_in[2];
    const float* eb1 = (const float*)d_in[3];
    const float* ew2 = (const float*)d_in[4];
    const float* eb2 = (const float*)d_in[5];
    const float* nw1 = (const float*)d_in[6];
    const float* nb1 = (const float*)d_in[7];
    const float* nw2 = (const float*)d_in[8];
    const float* nb2 = (const float*)d_in[9];
    const float* dw  = (const float*)d_in[10];
    const float* db  = (const float*)d_in[11];
    float*       out = (float*)d_out;

    static bool attr_done = false;
    if (!attr_done) {
        cudaFuncSetAttribute(edge_mlp_kernel,
            cudaFuncAttributeMaxDynamicSharedMemorySize, 60 * 1024);
        cudaFuncSetAttribute(node_mlp_kernel,
            cudaFuncAttributeMaxDynamicSharedMemorySize, 60 * 1024);
        attr_done = true;
    }

    const int node_smem = (IN_DIM + HID) * RS * (int)sizeof(float);            // 46.1 KB
    const int edge_smem = (2 * IN_DIM + HID) * RS * (int)sizeof(float)
                        + 2 * EPB * (int)sizeof(int);                          // 55.6 KB

    const int total_nodes = B * NNODE;                   // 100000
    const long long total_edges = (long long)B * NEDGE;  // 1000000

    detect_edge_dtype_kernel<<<1, 32>>>(e32);
    convert_edges_kernel<<<(NEDGE + 255) / 256, 256>>>(e32);
    node_mlp_kernel<<<total_nodes / MPB, 256, node_smem>>>(x, nw1, nb1, nw2, nb2);
    edge_mlp_kernel<<<(unsigned)(total_edges / EPB), 256, edge_smem>>>(x, ew1, eb1, ew2, eb2);
    decode_kernel<<<total_nodes / DPB, 256>>>(dw, db, out);
}

// round 6
// speedup vs baseline: 1.4115x; 1.4115x over previous
#include <cuda_runtime.h>
#include <cstdint>

#define B      2
#define NNODE  50000
#define IN_DIM 64
#define HID    256
#define OUT    128
#define NEDGE  500000
#define TOTAL_NODES (B * NNODE)

#define EPB 64           // edges per block
#define MPB 64           // nodes per block
#define DPB 16           // decode nodes per block
#define RS  68           // [k][m] tile row stride (floats, mult of 4)
#define HS_RS (HID + 4)  // hs [m][k] row stride = 260

// Scratch (__device__ globals: allocation-guard-safe)
__device__ float g_H[(size_t)B * NNODE * OUT];
__device__ int   g_eu[NEDGE];
__device__ int   g_ev[NEDGE];
__device__ int   g_is64;

// ---------------------------------------------------------------------------
// edge dtype detect + SoA normalize (proven)
// ---------------------------------------------------------------------------
__global__ void detect_edge_dtype_kernel(const int* __restrict__ e32)
{
    if (threadIdx.x == 0 && blockIdx.x == 0) {
        int all_zero = 1;
        #pragma unroll 1
        for (int i = 1; i < 256; i += 2)
            if (e32[i] != 0) { all_zero = 0; break; }
        g_is64 = all_zero;
    }
}

__global__ __launch_bounds__(256) void convert_edges_kernel(const int* __restrict__ e32)
{
    const int e = blockIdx.x * 256 + threadIdx.x;
    if (e < NEDGE) {
        if (g_is64) { g_eu[e] = e32[4 * e + 0]; g_ev[e] = e32[4 * e + 2]; }
        else        { g_eu[e] = e32[2 * e + 0]; g_ev[e] = e32[2 * e + 1]; }
    }
}

// ---------------------------------------------------------------------------
// Edge MLP v3: smem-staged GEMMs + atomic scatter.
//  smem: esT [2*IN_DIM][RS] (A1, [k][m]), hs [EPB][HS_RS] (A2, [m][k]),
//        ws [32][256] weight chunk (reused for GEMM2 as [32][128])
// ---------------------------------------------------------------------------
__global__ __launch_bounds__(512, 1) void edge_mlp_kernel(
    const float* __restrict__ x,
    const float* __restrict__ ew1, const float* __restrict__ eb1,
    const float* __restrict__ ew2, const float* __restrict__ eb2)
{
    extern __shared__ float sm[];
    float* esT = sm;                                   // 128*RS
    float* hs  = sm + 2 * IN_DIM * RS;                 // EPB*HS_RS
    float* ws  = hs + EPB * HS_RS;                     // 8192
    __shared__ int us[EPB], vs[EPB];

    const int t  = threadIdx.x;
    const int e0 = blockIdx.x * EPB;
    const int b  = blockIdx.y;
    const int count = min(EPB, NEDGE - e0);

    if (t < EPB) {
        int e = e0 + t; if (e >= NEDGE) e = NEDGE - 1;
        us[t] = g_eu[e]; vs[t] = g_ev[e];
    }
    __syncthreads();

    // gather concat(x[u],x[v]) into esT[k][m]
    const float* xb = x + (size_t)b * NNODE * IN_DIM;
    #pragma unroll
    for (int i = 0; i < 4; i++) {
        const int q  = t + i * 512;          // 2048 quads total
        const int m  = q >> 5;               // edge within tile
        const int c4 = (q & 31) * 4;         // col quad 0..124
        const int node = (c4 < IN_DIM) ? us[m] : vs[m];
        const float4 v = *(const float4*)&xb[(size_t)node * IN_DIM + (c4 & (IN_DIM - 1))];
        esT[(c4 + 0) * RS + m] = v.x;
        esT[(c4 + 1) * RS + m] = v.y;
        esT[(c4 + 2) * RS + m] = v.z;
        esT[(c4 + 3) * RS + m] = v.w;
    }

    // ---- GEMM1: [64m x 256n x 128k], thread tile 8m x 4n ----
    {
        const int m0 = (t >> 6) * 8;
        const int n0 = (t & 63) * 4;
        const float4 b1 = *(const float4*)&eb1[n0];
        float acc[8][4];
        #pragma unroll
        for (int i = 0; i < 8; i++) {
            acc[i][0] = b1.x; acc[i][1] = b1.y; acc[i][2] = b1.z; acc[i][3] = b1.w;
        }
        #pragma unroll 1
        for (int kc = 0; kc < 2 * IN_DIM / 32; kc++) {
            __syncthreads();
            {   // stage weight chunk [32][256]
                const float4* src = (const float4*)(ew1 + kc * 32 * HID);
                float4* dst = (float4*)ws;
                #pragma unroll
                for (int j = 0; j < 4; j++) dst[t + j * 512] = src[t + j * 512];
            }
            __syncthreads();
            const float* aT = esT + kc * 32 * RS;
            #pragma unroll 4
            for (int k = 0; k < 32; k++) {
                const float4 bv = *(const float4*)&ws[k * HID + n0];
                const float4 a0 = *(const float4*)&aT[k * RS + m0];
                const float4 a1 = *(const float4*)&aT[k * RS + m0 + 4];
                acc[0][0] = fmaf(a0.x, bv.x, acc[0][0]); acc[0][1] = fmaf(a0.x, bv.y, acc[0][1]);
                acc[0][2] = fmaf(a0.x, bv.z, acc[0][2]); acc[0][3] = fmaf(a0.x, bv.w, acc[0][3]);
                acc[1][0] = fmaf(a0.y, bv.x, acc[1][0]); acc[1][1] = fmaf(a0.y, bv.y, acc[1][1]);
                acc[1][2] = fmaf(a0.y, bv.z, acc[1][2]); acc[1][3] = fmaf(a0.y, bv.w, acc[1][3]);
                acc[2][0] = fmaf(a0.z, bv.x, acc[2][0]); acc[2][1] = fmaf(a0.z, bv.y, acc[2][1]);
                acc[2][2] = fmaf(a0.z, bv.z, acc[2][2]); acc[2][3] = fmaf(a0.z, bv.w, acc[2][3]);
                acc[3][0] = fmaf(a0.w, bv.x, acc[3][0]); acc[3][1] = fmaf(a0.w, bv.y, acc[3][1]);
                acc[3][2] = fmaf(a0.w, bv.z, acc[3][2]); acc[3][3] = fmaf(a0.w, bv.w, acc[3][3]);
                acc[4][0] = fmaf(a1.x, bv.x, acc[4][0]); acc[4][1] = fmaf(a1.x, bv.y, acc[4][1]);
                acc[4][2] = fmaf(a1.x, bv.z, acc[4][2]); acc[4][3] = fmaf(a1.x, bv.w, acc[4][3]);
                acc[5][0] = fmaf(a1.y, bv.x, acc[5][0]); acc[5][1] = fmaf(a1.y, bv.y, acc[5][1]);
                acc[5][2] = fmaf(a1.y, bv.z, acc[5][2]); acc[5][3] = fmaf(a1.y, bv.w, acc[5][3]);
                acc[6][0] = fmaf(a1.z, bv.x, acc[6][0]); acc[6][1] = fmaf(a1.z, bv.y, acc[6][1]);
                acc[6][2] = fmaf(a1.z, bv.z, acc[6][2]); acc[6][3] = fmaf(a1.z, bv.w, acc[6][3]);
                acc[7][0] = fmaf(a1.w, bv.x, acc[7][0]); acc[7][1] = fmaf(a1.w, bv.y, acc[7][1]);
                acc[7][2] = fmaf(a1.w, bv.z, acc[7][2]); acc[7][3] = fmaf(a1.w, bv.w, acc[7][3]);
            }
        }
        // relu + store hs[m][n] (coalesced float4, conflict-free)
        #pragma unroll
        for (int i = 0; i < 8; i++) {
            float4 r = make_float4(fmaxf(acc[i][0], 0.f), fmaxf(acc[i][1], 0.f),
                                   fmaxf(acc[i][2], 0.f), fmaxf(acc[i][3], 0.f));
            *(float4*)&hs[(m0 + i) * HS_RS + n0] = r;
        }
    }

    // ---- GEMM2: [64m x 128n x 256k], thread tile 4m x 4n, k-vectorized ----
    {
        const int m0 = (t >> 5) * 4;
        const int n0 = (t & 31) * 4;
        const float4 b2 = *(const float4*)&eb2[n0];
        float acc[4][4];
        #pragma unroll
        for (int i = 0; i < 4; i++) {
            acc[i][0] = b2.x; acc[i][1] = b2.y; acc[i][2] = b2.z; acc[i][3] = b2.w;
        }
        #pragma unroll 1
        for (int kc = 0; kc < HID / 32; kc++) {
            __syncthreads();
            {   // stage weight chunk [32][128]
                const float4* src = (const float4*)(ew2 + kc * 32 * OUT);
                float4* dst = (float4*)ws;
                #pragma unroll
                for (int j = 0; j < 2; j++) dst[t + j * 512] = src[t + j * 512];
            }
            __syncthreads();
            #pragma unroll 2
            for (int k4 = 0; k4 < 32; k4 += 4) {
                const float4 b0 = *(const float4*)&ws[(k4 + 0) * OUT + n0];
                const float4 b1v = *(const float4*)&ws[(k4 + 1) * OUT + n0];
                const float4 b2v = *(const float4*)&ws[(k4 + 2) * OUT + n0];
                const float4 b3v = *(const float4*)&ws[(k4 + 3) * OUT + n0];
                #pragma unroll
                for (int i = 0; i < 4; i++) {
                    const float4 a = *(const float4*)&hs[(m0 + i) * HS_RS + kc * 32 + k4];
                    acc[i][0] = fmaf(a.x, b0.x,  acc[i][0]);
                    acc[i][1] = fmaf(a.x, b0.y,  acc[i][1]);
                    acc[i][2] = fmaf(a.x, b0.z,  acc[i][2]);
                    acc[i][3] = fmaf(a.x, b0.w,  acc[i][3]);
                    acc[i][0] = fmaf(a.y, b1v.x, acc[i][0]);
                    acc[i][1] = fmaf(a.y, b1v.y, acc[i][1]);
                    acc[i][2] = fmaf(a.y, b1v.z, acc[i][2]);
                    acc[i][3] = fmaf(a.y, b1v.w, acc[i][3]);
                    acc[i][0] = fmaf(a.z, b2v.x, acc[i][0]);
                    acc[i][1] = fmaf(a.z, b2v.y, acc[i][1]);
                    acc[i][2] = fmaf(a.z, b2v.z, acc[i][2]);
                    acc[i][3] = fmaf(a.z, b2v.w, acc[i][3]);
                    acc[i][0] = fmaf(a.w, b3v.x, acc[i][0]);
                    acc[i][1] = fmaf(a.w, b3v.y, acc[i][1]);
                    acc[i][2] = fmaf(a.w, b3v.z, acc[i][2]);
                    acc[i][3] = fmaf(a.w, b3v.w, acc[i][3]);
                }
            }
        }
        // scatter
        float* Hb = g_H + (size_t)b * NNODE * OUT;
        #pragma unroll
        for (int i = 0; i < 4; i++) {
            const int m = m0 + i;
            if (m < count) {
                const int u = us[m], v = vs[m];
                float* pu = &Hb[(size_t)u * OUT + n0];
                float* pv = &Hb[(size_t)v * OUT + n0];
                #pragma unroll
                for (int j = 0; j < 4; j++) {
                    atomicAdd(pu + j, acc[i][j]);
                    atomicAdd(pv + j, acc[i][j]);
                }
            }
        }
    }
}

// ---------------------------------------------------------------------------
// Node MLP v3: same structure, K1=64, plain g_H stores
// ---------------------------------------------------------------------------
__global__ __launch_bounds__(512, 1) void node_mlp_kernel(
    const float* __restrict__ x,
    const float* __restrict__ nw1, const float* __restrict__ nb1,
    const float* __restrict__ nw2, const float* __restrict__ nb2)
{
    extern __shared__ float sm[];
    float* xsT = sm;                                   // IN_DIM*RS
    float* hs  = sm + IN_DIM * RS;                     // MPB*HS_RS
    float* ws  = hs + MPB * HS_RS;                     // 8192

    const int t    = threadIdx.x;
    const int base = blockIdx.x * MPB;

    // gather x into xsT[k][m]  (1024 quads)
    #pragma unroll
    for (int i = 0; i < 2; i++) {
        const int q  = t + i * 512;
        const int m  = q >> 4;               // 16 quads per node
        const int c4 = (q & 15) * 4;
        int row = base + m; if (row >= TOTAL_NODES) row = TOTAL_NODES - 1;
        const float4 v = *(const float4*)&x[(size_t)row * IN_DIM + c4];
        xsT[(c4 + 0) * RS + m] = v.x;
        xsT[(c4 + 1) * RS + m] = v.y;
        xsT[(c4 + 2) * RS + m] = v.z;
        xsT[(c4 + 3) * RS + m] = v.w;
    }

    // ---- GEMM1: [64m x 256n x 64k] ----
    {
        const int m0 = (t >> 6) * 8;
        const int n0 = (t & 63) * 4;
        const float4 b1 = *(const float4*)&nb1[n0];
        float acc[8][4];
        #pragma unroll
        for (int i = 0; i < 8; i++) {
            acc[i][0] = b1.x; acc[i][1] = b1.y; acc[i][2] = b1.z; acc[i][3] = b1.w;
        }
        #pragma unroll 1
        for (int kc = 0; kc < IN_DIM / 32; kc++) {
            __syncthreads();
            {
                const float4* src = (const float4*)(nw1 + kc * 32 * HID);
                float4* dst = (float4*)ws;
                #pragma unroll
                for (int j = 0; j < 4; j++) dst[t + j * 512] = src[t + j * 512];
            }
            __syncthreads();
            const float* aT = xsT + kc * 32 * RS;
            #pragma unroll 4
            for (int k = 0; k < 32; k++) {
                const float4 bv = *(const float4*)&ws[k * HID + n0];
                const float4 a0 = *(const float4*)&aT[k * RS + m0];
                const float4 a1 = *(const float4*)&aT[k * RS + m0 + 4];
                acc[0][0] = fmaf(a0.x, bv.x, acc[0][0]); acc[0][1] = fmaf(a0.x, bv.y, acc[0][1]);
                acc[0][2] = fmaf(a0.x, bv.z, acc[0][2]); acc[0][3] = fmaf(a0.x, bv.w, acc[0][3]);
                acc[1][0] = fmaf(a0.y, bv.x, acc[1][0]); acc[1][1] = fmaf(a0.y, bv.y, acc[1][1]);
                acc[1][2] = fmaf(a0.y, bv.z, acc[1][2]); acc[1][3] = fmaf(a0.y, bv.w, acc[1][3]);
                acc[2][0] = fmaf(a0.z, bv.x, acc[2][0]); acc[2][1] = fmaf(a0.z, bv.y, acc[2][1]);
                acc[2][2] = fmaf(a0.z, bv.z, acc[2][2]); acc[2][3] = fmaf(a0.z, bv.w, acc[2][3]);
                acc[3][0] = fmaf(a0.w, bv.x, acc[3][0]); acc[3][1] = fmaf(a0.w, bv.y, acc[3][1]);
                acc[3][2] = fmaf(a0.w, bv.z, acc[3][2]); acc[3][3] = fmaf(a0.w, bv.w, acc[3][3]);
                acc[4][0] = fmaf(a1.x, bv.x, acc[4][0]); acc[4][1] = fmaf(a1.x, bv.y, acc[4][1]);
                acc[4][2] = fmaf(a1.x, bv.z, acc[4][2]); acc[4][3] = fmaf(a1.x, bv.w, acc[4][3]);
                acc[5][0] = fmaf(a1.y, bv.x, acc[5][0]); acc[5][1] = fmaf(a1.y, bv.y, acc[5][1]);
                acc[5][2] = fmaf(a1.y, bv.z, acc[5][2]); acc[5][3] = fmaf(a1.y, bv.w, acc[5][3]);
                acc[6][0] = fmaf(a1.z, bv.x, acc[6][0]); acc[6][1] = fmaf(a1.z, bv.y, acc[6][1]);
                acc[6][2] = fmaf(a1.z, bv.z, acc[6][2]); acc[6][3] = fmaf(a1.z, bv.w, acc[6][3]);
                acc[7][0] = fmaf(a1.w, bv.x, acc[7][0]); acc[7][1] = fmaf(a1.w, bv.y, acc[7][1]);
                acc[7][2] = fmaf(a1.w, bv.z, acc[7][2]); acc[7][3] = fmaf(a1.w, bv.w, acc[7][3]);
            }
        }
        #pragma unroll
        for (int i = 0; i < 8; i++) {
            float4 r = make_float4(fmaxf(acc[i][0], 0.f), fmaxf(acc[i][1], 0.f),
                                   fmaxf(acc[i][2], 0.f), fmaxf(acc[i][3], 0.f));
            *(float4*)&hs[(m0 + i) * HS_RS + n0] = r;
        }
    }

    // ---- GEMM2: [64m x 128n x 256k] -> g_H ----
    {
        const int m0 = (t >> 5) * 4;
        const int n0 = (t & 31) * 4;
        const float4 b2 = *(const float4*)&nb2[n0];
        float acc[4][4];
        #pragma unroll
        for (int i = 0; i < 4; i++) {
            acc[i][0] = b2.x; acc[i][1] = b2.y; acc[i][2] = b2.z; acc[i][3] = b2.w;
        }
        #pragma unroll 1
        for (int kc = 0; kc < HID / 32; kc++) {
            __syncthreads();
            {
                const float4* src = (const float4*)(nw2 + kc * 32 * OUT);
                float4* dst = (float4*)ws;
                #pragma unroll
                for (int j = 0; j < 2; j++) dst[t + j * 512] = src[t + j * 512];
            }
            __syncthreads();
            #pragma unroll 2
            for (int k4 = 0; k4 < 32; k4 += 4) {
                const float4 b0 = *(const float4*)&ws[(k4 + 0) * OUT + n0];
                const float4 b1v = *(const float4*)&ws[(k4 + 1) * OUT + n0];
                const float4 b2v = *(const float4*)&ws[(k4 + 2) * OUT + n0];
                const float4 b3v = *(const float4*)&ws[(k4 + 3) * OUT + n0];
                #pragma unroll
                for (int i = 0; i < 4; i++) {
                    const float4 a = *(const float4*)&hs[(m0 + i) * HS_RS + kc * 32 + k4];
                    acc[i][0] = fmaf(a.x, b0.x,  acc[i][0]);
                    acc[i][1] = fmaf(a.x, b0.y,  acc[i][1]);
                    acc[i][2] = fmaf(a.x, b0.z,  acc[i][2]);
                    acc[i][3] = fmaf(a.x, b0.w,  acc[i][3]);
                    acc[i][0] = fmaf(a.y, b1v.x, acc[i][0]);
                    acc[i][1] = fmaf(a.y, b1v.y, acc[i][1]);
                    acc[i][2] = fmaf(a.y, b1v.z, acc[i][2]);
                    acc[i][3] = fmaf(a.y, b1v.w, acc[i][3]);
                    acc[i][0] = fmaf(a.z, b2v.x, acc[i][0]);
                    acc[i][1] = fmaf(a.z, b2v.y, acc[i][1]);
                    acc[i][2] = fmaf(a.z, b2v.z, acc[i][2]);
                    acc[i][3] = fmaf(a.z, b2v.w, acc[i][3]);
                    acc[i][0] = fmaf(a.w, b3v.x, acc[i][0]);
                    acc[i][1] = fmaf(a.w, b3v.y, acc[i][1]);
                    acc[i][2] = fmaf(a.w, b3v.z, acc[i][2]);
                    acc[i][3] = fmaf(a.w, b3v.w, acc[i][3]);
                }
            }
        }
        #pragma unroll
        for (int i = 0; i < 4; i++) {
            const int row = base + m0 + i;
            if (row < TOTAL_NODES)
                *(float4*)&g_H[(size_t)row * OUT + n0] =
                    make_float4(acc[i][0], acc[i][1], acc[i][2], acc[i][3]);
        }
    }
}

// ---------------------------------------------------------------------------
// decode: out = H @ dw + db (unchanged)
// ---------------------------------------------------------------------------
__global__ __launch_bounds__(256) void decode_kernel(
    const float* __restrict__ dw, const float* __restrict__ db,
    float* __restrict__ out)
{
    __shared__ __align__(16) float hsm[DPB][OUT];

    const int base = blockIdx.x * DPB;
    const int t = threadIdx.x;

    for (int i = t; i < DPB * OUT; i += 256)
        hsm[i / OUT][i % OUT] = g_H[(size_t)base * OUT + i];
    __syncthreads();

    const int o   = t & (IN_DIM - 1);
    const int nb0 = (t >> 6) * (DPB / 4);
    float acc[DPB / 4];
    {
        const float bb = db[o];
        #pragma unroll
        for (int n = 0; n < DPB / 4; n++) acc[n] = bb;
    }
    #pragma unroll 4
    for (int k = 0; k < OUT; k += 4) {
        const float w0 = dw[(k + 0) * IN_DIM + o];
        const float w1 = dw[(k + 1) * IN_DIM + o];
        const float w2 = dw[(k + 2) * IN_DIM + o];
        const float w3 = dw[(k + 3) * IN_DIM + o];
        #pragma unroll
        for (int n = 0; n < DPB / 4; n++) {
            float4 v = *reinterpret_cast<const float4*>(&hsm[nb0 + n][k]);
            acc[n] = fmaf(v.x, w0, acc[n]);
            acc[n] = fmaf(v.y, w1, acc[n]);
            acc[n] = fmaf(v.z, w2, acc[n]);
            acc[n] = fmaf(v.w, w3, acc[n]);
        }
    }
    #pragma unroll
    for (int n = 0; n < DPB / 4; n++)
        out[(size_t)(base + nb0 + n) * IN_DIM + o] = acc[n];
}

// ---------------------------------------------------------------------------
extern "C" void kernel_launch(void* const* d_in, const int* in_sizes, int n_in,
                              void* d_out, int out_size)
{
    const float* x   = (const float*)d_in[0];
    const int*   e32 = (const int*)d_in[1];
    const float* ew1 = (const float*)d_in[2];
    const float* eb1 = (const float*)d_in[3];
    const float* ew2 = (const float*)d_in[4];
    const float* eb2 = (const float*)d_in[5];
    const float* nw1 = (const float*)d_in[6];
    const float* nb1 = (const float*)d_in[7];
    const float* nw2 = (const float*)d_in[8];
    const float* nb2 = (const float*)d_in[9];
    const float* dw  = (const float*)d_in[10];
    const float* db  = (const float*)d_in[11];
    float*       out = (float*)d_out;

    const int edge_smem = (2 * IN_DIM * RS + EPB * HS_RS + 32 * HID) * (int)sizeof(float); // 134144
    const int node_smem = (IN_DIM * RS + MPB * HS_RS + 32 * HID) * (int)sizeof(float);     // 116736

    static bool attr_done = false;
    if (!attr_done) {
        cudaFuncSetAttribute(edge_mlp_kernel,
            cudaFuncAttributeMaxDynamicSharedMemorySize, edge_smem);
        cudaFuncSetAttribute(node_mlp_kernel,
            cudaFuncAttributeMaxDynamicSharedMemorySize, node_smem);
        attr_done = true;
    }

    detect_edge_dtype_kernel<<<1, 32>>>(e32);
    convert_edges_kernel<<<(NEDGE + 255) / 256, 256>>>(e32);

    node_mlp_kernel<<<(TOTAL_NODES + MPB - 1) / MPB, 512, node_smem>>>(x, nw1, nb1, nw2, nb2);

    dim3 egrid((NEDGE + EPB - 1) / EPB, B);
    edge_mlp_kernel<<<egrid, 512, edge_smem>>>(x, ew1, eb1, ew2, eb2);

    decode_kernel<<<TOTAL_NODES / DPB, 256>>>(dw, db, out);
}

// round 7
// speedup vs baseline: 1.6766x; 1.1878x over previous
#include <cuda_runtime.h>
#include <cstdint>

#define B      2
#define NNODE  50000
#define IN_DIM 64
#define HID    256
#define OUT    128
#define NEDGE  500000
#define TOTAL_NODES (B * NNODE)

#define EPB 32           // edges per block
#define MPB 32           // nodes per block
#define DPB 16           // decode nodes per block
#define RS  36           // [k][m] A-tile row stride (floats, mult of 4)
#define HS_RS (HID + 4)  // hs [m][k] row stride = 260 (mult of 4)

// Scratch (__device__ globals: allocation-guard-safe)
__device__ float g_H[(size_t)B * NNODE * OUT];
__device__ int   g_eu[NEDGE];
__device__ int   g_ev[NEDGE];
__device__ int   g_is64;

// vectorized global reduction (sm_90+): one request per 16B
static __device__ __forceinline__ void red_add_v4(float* p, float a, float b, float c, float d)
{
    asm volatile("red.global.add.v4.f32 [%0], {%1, %2, %3, %4};"
                 :: "l"(p), "f"(a), "f"(b), "f"(c), "f"(d) : "memory");
}

// ---------------------------------------------------------------------------
// edge dtype detect + SoA normalize (proven)
// ---------------------------------------------------------------------------
__global__ void detect_edge_dtype_kernel(const int* __restrict__ e32)
{
    if (threadIdx.x == 0 && blockIdx.x == 0) {
        int all_zero = 1;
        #pragma unroll 1
        for (int i = 1; i < 256; i += 2)
            if (e32[i] != 0) { all_zero = 0; break; }
        g_is64 = all_zero;
    }
}

__global__ __launch_bounds__(256) void convert_edges_kernel(const int* __restrict__ e32)
{
    const int e = blockIdx.x * 256 + threadIdx.x;
    if (e < NEDGE) {
        if (g_is64) { g_eu[e] = e32[4 * e + 0]; g_ev[e] = e32[4 * e + 2]; }
        else        { g_eu[e] = e32[2 * e + 0]; g_ev[e] = e32[2 * e + 1]; }
    }
}

// ---------------------------------------------------------------------------
// Edge MLP v4: 256 threads, EPB=32, 68.1 KB smem -> 3 CTAs/SM.
//  esT [128][RS]  (A1, [k][m])
//  hs  [EPB][HS_RS] (A2, [m][k])
//  ws  16*256 floats (GEMM1 chunk 16 rows; GEMM2 chunk 32x128 = same bytes)
// ---------------------------------------------------------------------------
__global__ __launch_bounds__(256, 3) void edge_mlp_kernel(
    const float* __restrict__ x,
    const float* __restrict__ ew1, const float* __restrict__ eb1,
    const float* __restrict__ ew2, const float* __restrict__ eb2)
{
    extern __shared__ float sm[];
    float* esT = sm;                              // 128*RS = 4608
    float* hs  = sm + 2 * IN_DIM * RS;            // 32*260 = 8320
    float* ws  = hs + EPB * HS_RS;                // 4096
    __shared__ int us[EPB], vs[EPB];

    const int t  = threadIdx.x;
    const int e0 = blockIdx.x * EPB;
    const int b  = blockIdx.y;

    if (t < EPB) { us[t] = g_eu[e0 + t]; vs[t] = g_ev[e0 + t]; }
    __syncthreads();

    // gather concat(x[u],x[v]) into esT[k][m]: 1024 quads, coalesced LDG per node row
    const float* xb = x + (size_t)b * NNODE * IN_DIM;
    #pragma unroll
    for (int i = 0; i < 4; i++) {
        const int q  = t + i * 256;
        const int m  = q >> 5;               // edge in tile (uniform per warp)
        const int c4 = (q & 31) * 4;         // col quad
        const int node = (c4 < IN_DIM) ? us[m] : vs[m];
        const float4 v = *(const float4*)&xb[(size_t)node * IN_DIM + (c4 & (IN_DIM - 1))];
        esT[(c4 + 0) * RS + m] = v.x;
        esT[(c4 + 1) * RS + m] = v.y;
        esT[(c4 + 2) * RS + m] = v.z;
        esT[(c4 + 3) * RS + m] = v.w;
    }

    // ---- GEMM1: [32m x 256n x 128k], thread tile 8m x 4n, weight chunks 16 ----
    {
        const int m0 = (t >> 6) * 8;   // uniform per warp -> broadcast A
        const int n0 = (t & 63) * 4;
        const float4 b1 = *(const float4*)&eb1[n0];
        float acc[8][4];
        #pragma unroll
        for (int i = 0; i < 8; i++) {
            acc[i][0] = b1.x; acc[i][1] = b1.y; acc[i][2] = b1.z; acc[i][3] = b1.w;
        }
        #pragma unroll 1
        for (int kc = 0; kc < 2 * IN_DIM / 16; kc++) {
            __syncthreads();
            {   // stage weight chunk [16][256] = 1024 float4
                const float4* src = (const float4*)(ew1 + kc * 16 * HID);
                float4* dst = (float4*)ws;
                #pragma unroll
                for (int j = 0; j < 4; j++) dst[t + j * 256] = src[t + j * 256];
            }
            __syncthreads();
            const float* aT = esT + kc * 16 * RS;
            #pragma unroll 4
            for (int k = 0; k < 16; k++) {
                const float4 bv = *(const float4*)&ws[k * HID + n0];
                const float4 a0 = *(const float4*)&aT[k * RS + m0];
                const float4 a1 = *(const float4*)&aT[k * RS + m0 + 4];
                acc[0][0] = fmaf(a0.x, bv.x, acc[0][0]); acc[0][1] = fmaf(a0.x, bv.y, acc[0][1]);
                acc[0][2] = fmaf(a0.x, bv.z, acc[0][2]); acc[0][3] = fmaf(a0.x, bv.w, acc[0][3]);
                acc[1][0] = fmaf(a0.y, bv.x, acc[1][0]); acc[1][1] = fmaf(a0.y, bv.y, acc[1][1]);
                acc[1][2] = fmaf(a0.y, bv.z, acc[1][2]); acc[1][3] = fmaf(a0.y, bv.w, acc[1][3]);
                acc[2][0] = fmaf(a0.z, bv.x, acc[2][0]); acc[2][1] = fmaf(a0.z, bv.y, acc[2][1]);
                acc[2][2] = fmaf(a0.z, bv.z, acc[2][2]); acc[2][3] = fmaf(a0.z, bv.w, acc[2][3]);
                acc[3][0] = fmaf(a0.w, bv.x, acc[3][0]); acc[3][1] = fmaf(a0.w, bv.y, acc[3][1]);
                acc[3][2] = fmaf(a0.w, bv.z, acc[3][2]); acc[3][3] = fmaf(a0.w, bv.w, acc[3][3]);
                acc[4][0] = fmaf(a1.x, bv.x, acc[4][0]); acc[4][1] = fmaf(a1.x, bv.y, acc[4][1]);
                acc[4][2] = fmaf(a1.x, bv.z, acc[4][2]); acc[4][3] = fmaf(a1.x, bv.w, acc[4][3]);
                acc[5][0] = fmaf(a1.y, bv.x, acc[5][0]); acc[5][1] = fmaf(a1.y, bv.y, acc[5][1]);
                acc[5][2] = fmaf(a1.y, bv.z, acc[5][2]); acc[5][3] = fmaf(a1.y, bv.w, acc[5][3]);
                acc[6][0] = fmaf(a1.z, bv.x, acc[6][0]); acc[6][1] = fmaf(a1.z, bv.y, acc[6][1]);
                acc[6][2] = fmaf(a1.z, bv.z, acc[6][2]); acc[6][3] = fmaf(a1.z, bv.w, acc[6][3]);
                acc[7][0] = fmaf(a1.w, bv.x, acc[7][0]); acc[7][1] = fmaf(a1.w, bv.y, acc[7][1]);
                acc[7][2] = fmaf(a1.w, bv.z, acc[7][2]); acc[7][3] = fmaf(a1.w, bv.w, acc[7][3]);
            }
        }
        // relu + store hs[m][n]: lanes span 512B consecutive -> conflict-free
        #pragma unroll
        for (int i = 0; i < 8; i++) {
            float4 r = make_float4(fmaxf(acc[i][0], 0.f), fmaxf(acc[i][1], 0.f),
                                   fmaxf(acc[i][2], 0.f), fmaxf(acc[i][3], 0.f));
            *(float4*)&hs[(m0 + i) * HS_RS + n0] = r;
        }
    }

    // ---- GEMM2: [32m x 128n x 256k], thread tile 4m x 4n, weight chunks 32 ----
    {
        const int m0 = (t >> 5) * 4;   // uniform per warp -> broadcast A
        const int n0 = (t & 31) * 4;
        const float4 b2 = *(const float4*)&eb2[n0];
        float acc[4][4];
        #pragma unroll
        for (int i = 0; i < 4; i++) {
            acc[i][0] = b2.x; acc[i][1] = b2.y; acc[i][2] = b2.z; acc[i][3] = b2.w;
        }
        #pragma unroll 1
        for (int kc = 0; kc < HID / 32; kc++) {
            __syncthreads();
            {   // stage weight chunk [32][128] = 1024 float4
                const float4* src = (const float4*)(ew2 + kc * 32 * OUT);
                float4* dst = (float4*)ws;
                #pragma unroll
                for (int j = 0; j < 4; j++) dst[t + j * 256] = src[t + j * 256];
            }
            __syncthreads();
            #pragma unroll 2
            for (int k4 = 0; k4 < 32; k4 += 4) {
                const float4 b0  = *(const float4*)&ws[(k4 + 0) * OUT + n0];
                const float4 b1v = *(const float4*)&ws[(k4 + 1) * OUT + n0];
                const float4 b2v = *(const float4*)&ws[(k4 + 2) * OUT + n0];
                const float4 b3v = *(const float4*)&ws[(k4 + 3) * OUT + n0];
                #pragma unroll
                for (int i = 0; i < 4; i++) {
                    const float4 a = *(const float4*)&hs[(m0 + i) * HS_RS + kc * 32 + k4];
                    acc[i][0] = fmaf(a.x, b0.x,  acc[i][0]);
                    acc[i][1] = fmaf(a.x, b0.y,  acc[i][1]);
                    acc[i][2] = fmaf(a.x, b0.z,  acc[i][2]);
                    acc[i][3] = fmaf(a.x, b0.w,  acc[i][3]);
                    acc[i][0] = fmaf(a.y, b1v.x, acc[i][0]);
                    acc[i][1] = fmaf(a.y, b1v.y, acc[i][1]);
                    acc[i][2] = fmaf(a.y, b1v.z, acc[i][2]);
                    acc[i][3] = fmaf(a.y, b1v.w, acc[i][3]);
                    acc[i][0] = fmaf(a.z, b2v.x, acc[i][0]);
                    acc[i][1] = fmaf(a.z, b2v.y, acc[i][1]);
                    acc[i][2] = fmaf(a.z, b2v.z, acc[i][2]);
                    acc[i][3] = fmaf(a.z, b2v.w, acc[i][3]);
                    acc[i][0] = fmaf(a.w, b3v.x, acc[i][0]);
                    acc[i][1] = fmaf(a.w, b3v.y, acc[i][1]);
                    acc[i][2] = fmaf(a.w, b3v.z, acc[i][2]);
                    acc[i][3] = fmaf(a.w, b3v.w, acc[i][3]);
                }
            }
        }
        // vectorized scatter: one red.v4 per 16B
        float* Hb = g_H + (size_t)b * NNODE * OUT;
        #pragma unroll
        for (int i = 0; i < 4; i++) {
            const int m = m0 + i;
            const int u = us[m], v = vs[m];
            red_add_v4(&Hb[(size_t)u * OUT + n0], acc[i][0], acc[i][1], acc[i][2], acc[i][3]);
            red_add_v4(&Hb[(size_t)v * OUT + n0], acc[i][0], acc[i][1], acc[i][2], acc[i][3]);
        }
    }
}

// ---------------------------------------------------------------------------
// Node MLP v4: same structure, K1=64, plain stores
// ---------------------------------------------------------------------------
__global__ __launch_bounds__(256, 3) void node_mlp_kernel(
    const float* __restrict__ x,
    const float* __restrict__ nw1, const float* __restrict__ nb1,
    const float* __restrict__ nw2, const float* __restrict__ nb2)
{
    extern __shared__ float sm[];
    float* xsT = sm;                              // 64*RS = 2304
    float* hs  = sm + IN_DIM * RS;                // 32*260 = 8320
    float* ws  = hs + MPB * HS_RS;                // 4096

    const int t    = threadIdx.x;
    const int base = blockIdx.x * MPB;

    // gather x into xsT[k][m]: 512 quads
    #pragma unroll
    for (int i = 0; i < 2; i++) {
        const int q  = t + i * 256;
        const int m  = q >> 4;
        const int c4 = (q & 15) * 4;
        const float4 v = *(const float4*)&x[(size_t)(base + m) * IN_DIM + c4];
        xsT[(c4 + 0) * RS + m] = v.x;
        xsT[(c4 + 1) * RS + m] = v.y;
        xsT[(c4 + 2) * RS + m] = v.z;
        xsT[(c4 + 3) * RS + m] = v.w;
    }

    // ---- GEMM1: [32m x 256n x 64k] ----
    {
        const int m0 = (t >> 6) * 8;
        const int n0 = (t & 63) * 4;
        const float4 b1 = *(const float4*)&nb1[n0];
        float acc[8][4];
        #pragma unroll
        for (int i = 0; i < 8; i++) {
            acc[i][0] = b1.x; acc[i][1] = b1.y; acc[i][2] = b1.z; acc[i][3] = b1.w;
        }
        #pragma unroll 1
        for (int kc = 0; kc < IN_DIM / 16; kc++) {
            __syncthreads();
            {
                const float4* src = (const float4*)(nw1 + kc * 16 * HID);
                float4* dst = (float4*)ws;
                #pragma unroll
                for (int j = 0; j < 4; j++) dst[t + j * 256] = src[t + j * 256];
            }
            __syncthreads();
            const float* aT = xsT + kc * 16 * RS;
            #pragma unroll 4
            for (int k = 0; k < 16; k++) {
                const float4 bv = *(const float4*)&ws[k * HID + n0];
                const float4 a0 = *(const float4*)&aT[k * RS + m0];
                const float4 a1 = *(const float4*)&aT[k * RS + m0 + 4];
                acc[0][0] = fmaf(a0.x, bv.x, acc[0][0]); acc[0][1] = fmaf(a0.x, bv.y, acc[0][1]);
                acc[0][2] = fmaf(a0.x, bv.z, acc[0][2]); acc[0][3] = fmaf(a0.x, bv.w, acc[0][3]);
                acc[1][0] = fmaf(a0.y, bv.x, acc[1][0]); acc[1][1] = fmaf(a0.y, bv.y, acc[1][1]);
                acc[1][2] = fmaf(a0.y, bv.z, acc[1][2]); acc[1][3] = fmaf(a0.y, bv.w, acc[1][3]);
                acc[2][0] = fmaf(a0.z, bv.x, acc[2][0]); acc[2][1] = fmaf(a0.z, bv.y, acc[2][1]);
                acc[2][2] = fmaf(a0.z, bv.z, acc[2][2]); acc[2][3] = fmaf(a0.z, bv.w, acc[2][3]);
                acc[3][0] = fmaf(a0.w, bv.x, acc[3][0]); acc[3][1] = fmaf(a0.w, bv.y, acc[3][1]);
                acc[3][2] = fmaf(a0.w, bv.z, acc[3][2]); acc[3][3] = fmaf(a0.w, bv.w, acc[3][3]);
                acc[4][0] = fmaf(a1.x, bv.x, acc[4][0]); acc[4][1] = fmaf(a1.x, bv.y, acc[4][1]);
                acc[4][2] = fmaf(a1.x, bv.z, acc[4][2]); acc[4][3] = fmaf(a1.x, bv.w, acc[4][3]);
                acc[5][0] = fmaf(a1.y, bv.x, acc[5][0]); acc[5][1] = fmaf(a1.y, bv.y, acc[5][1]);
                acc[5][2] = fmaf(a1.y, bv.z, acc[5][2]); acc[5][3] = fmaf(a1.y, bv.w, acc[5][3]);
                acc[6][0] = fmaf(a1.z, bv.x, acc[6][0]); acc[6][1] = fmaf(a1.z, bv.y, acc[6][1]);
                acc[6][2] = fmaf(a1.z, bv.z, acc[6][2]); acc[6][3] = fmaf(a1.z, bv.w, acc[6][3]);
                acc[7][0] = fmaf(a1.w, bv.x, acc[7][0]); acc[7][1] = fmaf(a1.w, bv.y, acc[7][1]);
                acc[7][2] = fmaf(a1.w, bv.z, acc[7][2]); acc[7][3] = fmaf(a1.w, bv.w, acc[7][3]);
            }
        }
        #pragma unroll
        for (int i = 0; i < 8; i++) {
            float4 r = make_float4(fmaxf(acc[i][0], 0.f), fmaxf(acc[i][1], 0.f),
                                   fmaxf(acc[i][2], 0.f), fmaxf(acc[i][3], 0.f));
            *(float4*)&hs[(m0 + i) * HS_RS + n0] = r;
        }
    }

    // ---- GEMM2: [32m x 128n x 256k] -> g_H ----
    {
        const int m0 = (t >> 5) * 4;
        const int n0 = (t & 31) * 4;
        const float4 b2 = *(const float4*)&nb2[n0];
        float acc[4][4];
        #pragma unroll
        for (int i = 0; i < 4; i++) {
            acc[i][0] = b2.x; acc[i][1] = b2.y; acc[i][2] = b2.z; acc[i][3] = b2.w;
        }
        #pragma unroll 1
        for (int kc = 0; kc < HID / 32; kc++) {
            __syncthreads();
            {
                const float4* src = (const float4*)(nw2 + kc * 32 * OUT);
                float4* dst = (float4*)ws;
                #pragma unroll
                for (int j = 0; j < 4; j++) dst[t + j * 256] = src[t + j * 256];
            }
            __syncthreads();
            #pragma unroll 2
            for (int k4 = 0; k4 < 32; k4 += 4) {
                const float4 b0  = *(const float4*)&ws[(k4 + 0) * OUT + n0];
                const float4 b1v = *(const float4*)&ws[(k4 + 1) * OUT + n0];
                const float4 b2v = *(const float4*)&ws[(k4 + 2) * OUT + n0];
                const float4 b3v = *(const float4*)&ws[(k4 + 3) * OUT + n0];
                #pragma unroll
                for (int i = 0; i < 4; i++) {
                    const float4 a = *(const float4*)&hs[(m0 + i) * HS_RS + kc * 32 + k4];
                    acc[i][0] = fmaf(a.x, b0.x,  acc[i][0]);
                    acc[i][1] = fmaf(a.x, b0.y,  acc[i][1]);
                    acc[i][2] = fmaf(a.x, b0.z,  acc[i][2]);
                    acc[i][3] = fmaf(a.x, b0.w,  acc[i][3]);
                    acc[i][0] = fmaf(a.y, b1v.x, acc[i][0]);
                    acc[i][1] = fmaf(a.y, b1v.y, acc[i][1]);
                    acc[i][2] = fmaf(a.y, b1v.z, acc[i][2]);
                    acc[i][3] = fmaf(a.y, b1v.w, acc[i][3]);
                    acc[i][0] = fmaf(a.z, b2v.x, acc[i][0]);
                    acc[i][1] = fmaf(a.z, b2v.y, acc[i][1]);
                    acc[i][2] = fmaf(a.z, b2v.z, acc[i][2]);
                    acc[i][3] = fmaf(a.z, b2v.w, acc[i][3]);
                    acc[i][0] = fmaf(a.w, b3v.x, acc[i][0]);
                    acc[i][1] = fmaf(a.w, b3v.y, acc[i][1]);
                    acc[i][2] = fmaf(a.w, b3v.z, acc[i][2]);
                    acc[i][3] = fmaf(a.w, b3v.w, acc[i][3]);
                }
            }
        }
        #pragma unroll
        for (int i = 0; i < 4; i++)
            *(float4*)&g_H[(size_t)(base + m0 + i) * OUT + n0] =
                make_float4(acc[i][0], acc[i][1], acc[i][2], acc[i][3]);
    }
}

// ---------------------------------------------------------------------------
// decode: out = H @ dw + db (unchanged)
// ---------------------------------------------------------------------------
__global__ __launch_bounds__(256) void decode_kernel(
    const float* __restrict__ dw, const float* __restrict__ db,
    float* __restrict__ out)
{
    __shared__ __align__(16) float hsm[DPB][OUT];

    const int base = blockIdx.x * DPB;
    const int t = threadIdx.x;

    for (int i = t; i < DPB * OUT; i += 256)
        hsm[i / OUT][i % OUT] = g_H[(size_t)base * OUT + i];
    __syncthreads();

    const int o   = t & (IN_DIM - 1);
    const int nb0 = (t >> 6) * (DPB / 4);
    float acc[DPB / 4];
    {
        const float bb = db[o];
        #pragma unroll
        for (int n = 0; n < DPB / 4; n++) acc[n] = bb;
    }
    #pragma unroll 4
    for (int k = 0; k < OUT; k += 4) {
        const float w0 = dw[(k + 0) * IN_DIM + o];
        const float w1 = dw[(k + 1) * IN_DIM + o];
        const float w2 = dw[(k + 2) * IN_DIM + o];
        const float w3 = dw[(k + 3) * IN_DIM + o];
        #pragma unroll
        for (int n = 0; n < DPB / 4; n++) {
            float4 v = *reinterpret_cast<const float4*>(&hsm[nb0 + n][k]);
            acc[n] = fmaf(v.x, w0, acc[n]);
            acc[n] = fmaf(v.y, w1, acc[n]);
            acc[n] = fmaf(v.z, w2, acc[n]);
            acc[n] = fmaf(v.w, w3, acc[n]);
        }
    }
    #pragma unroll
    for (int n = 0; n < DPB / 4; n++)
        out[(size_t)(base + nb0 + n) * IN_DIM + o] = acc[n];
}

// ---------------------------------------------------------------------------
extern "C" void kernel_launch(void* const* d_in, const int* in_sizes, int n_in,
                              void* d_out, int out_size)
{
    const float* x   = (const float*)d_in[0];
    const int*   e32 = (const int*)d_in[1];
    const float* ew1 = (const float*)d_in[2];
    const float* eb1 = (const float*)d_in[3];
    const float* ew2 = (const float*)d_in[4];
    const float* eb2 = (const float*)d_in[5];
    const float* nw1 = (const float*)d_in[6];
    const float* nb1 = (const float*)d_in[7];
    const float* nw2 = (const float*)d_in[8];
    const float* nb2 = (const float*)d_in[9];
    const float* dw  = (const float*)d_in[10];
    const float* db  = (const float*)d_in[11];
    float*       out = (float*)d_out;

    const int edge_smem = (2 * IN_DIM * RS + EPB * HS_RS + 16 * HID) * (int)sizeof(float); // 68096
    const int node_smem = (IN_DIM * RS + MPB * HS_RS + 16 * HID) * (int)sizeof(float);     // 58880

    static bool attr_done = false;
    if (!attr_done) {
        cudaFuncSetAttribute(edge_mlp_kernel,
            cudaFuncAttributeMaxDynamicSharedMemorySize, edge_smem);
        cudaFuncSetAttribute(node_mlp_kernel,
            cudaFuncAttributeMaxDynamicSharedMemorySize, node_smem);
        attr_done = true;
    }

    detect_edge_dtype_kernel<<<1, 32>>>(e32);
    convert_edges_kernel<<<(NEDGE + 255) / 256, 256>>>(e32);

    node_mlp_kernel<<<TOTAL_NODES / MPB, 256, node_smem>>>(x, nw1, nb1, nw2, nb2);

    dim3 egrid(NEDGE / EPB, B);
    edge_mlp_kernel<<<egrid, 256, edge_smem>>>(x, ew1, eb1, ew2, eb2);

    decode_kernel<<<TOTAL_NODES / DPB, 256>>>(dw, db, out);
}

// round 9
// speedup vs baseline: 1.8024x; 1.0750x over previous
#include <cuda_runtime.h>
#include <cuda_bf16.h>
#include <cstdint>

#define B      2
#define NNODE  50000
#define IN_DIM 64
#define HID    256
#define OUT    128
#define NEDGE  500000
#define TOTAL_NODES (B * NNODE)

// fp32 node/decode tiles (proven R7 config)
#define MPB 32
#define DPB 16
#define RS  36
#define HS_RS (HID + 4)

// edge tensor kernel
#define ET_M  64                   // edges per block
#define KS1   264                  // As1/Bs1 row stride (bf16): 128 hi + 128 lo + 8 pad
#define KS2   536                  // As2/Bs2 row stride (bf16): 256 hi + 256 lo + 24 pad
#define DS    68                   // Dh row stride (f32)
// dynamic smem offsets (bytes)
#define OFF_AS1  0                 // 64*264*2  = 33792
#define OFF_BS1  33792             // 128*264*2 = 67584  -> ends 101376
#define OFF_AS2  101376            // 64*536*2  = 68608  -> ends 169984
#define OFF_BS2  0                 // 64*536*2  = 68608 (reuse As1+Bs1)
#define OFF_DH   69632             // 64*68*4   = 17408 (ends 87040)
#define EDGE_DSMEM 169984

// ---------------------------------------------------------------------------
// device globals (allocation-guard-safe)
// ---------------------------------------------------------------------------
__device__ float g_H[(size_t)B * NNODE * OUT];
__device__ int   g_eu[NEDGE];
__device__ int   g_ev[NEDGE];
__device__ int   g_is64;
// pre-split, pre-transposed bf16 weight images:
// g_B1bf[n][k']: n 0..255, k' = k (hi) | 128+k (lo) of ew1[k][n], k 0..127
// g_B2bf[n][k']: n 0..127, k' = k (hi) | 256+k (lo) of ew2[k][n], k 0..255
__device__ __align__(16) __nv_bfloat16 g_B1bf[256 * KS1];
__device__ __align__(16) __nv_bfloat16 g_B2bf[128 * KS2];

// ---------------------------------------------------------------------------
// helpers
// ---------------------------------------------------------------------------
static __device__ __forceinline__ void mma16816(float* d, const uint32_t* a, const uint32_t* b)
{
    asm volatile(
        "mma.sync.aligned.m16n8k16.row.col.f32.bf16.bf16.f32 "
        "{%0,%1,%2,%3}, {%4,%5,%6,%7}, {%8,%9}, {%0,%1,%2,%3};"
        : "+f"(d[0]), "+f"(d[1]), "+f"(d[2]), "+f"(d[3])
        : "r"(a[0]), "r"(a[1]), "r"(a[2]), "r"(a[3]), "r"(b[0]), "r"(b[1]));
}

static __device__ __forceinline__ void red_add_v4(float* p, float a, float b, float c, float d)
{
    asm volatile("red.global.add.v4.f32 [%0], {%1, %2, %3, %4};"
                 :: "l"(p), "f"(a), "f"(b), "f"(c), "f"(d) : "memory");
}

// split v0,v1 into bf16 hi/lo pairs and store as packed u32
static __device__ __forceinline__ void split_store(__nv_bfloat16* hi_p, __nv_bfloat16* lo_p,
                                                   float v0, float v1)
{
    __nv_bfloat162 hp = __floats2bfloat162_rn(v0, v1);
    const float h0 = __bfloat162float(hp.x), h1 = __bfloat162float(hp.y);
    __nv_bfloat162 lp = __floats2bfloat162_rn(v0 - h0, v1 - h1);
    *(uint32_t*)hi_p = *(const uint32_t*)&hp;
    *(uint32_t*)lo_p = *(const uint32_t*)&lp;
}

// ---------------------------------------------------------------------------
// edge dtype detect + SoA normalize (proven)
// ---------------------------------------------------------------------------
__global__ void detect_edge_dtype_kernel(const int* __restrict__ e32)
{
    if (threadIdx.x == 0 && blockIdx.x == 0) {
        int all_zero = 1;
        #pragma unroll 1
        for (int i = 1; i < 256; i += 2)
            if (e32[i] != 0) { all_zero = 0; break; }
        g_is64 = all_zero;
    }
}

__global__ __launch_bounds__(256) void convert_edges_kernel(const int* __restrict__ e32)
{
    const int e = blockIdx.x * 256 + threadIdx.x;
    if (e < NEDGE) {
        if (g_is64) { g_eu[e] = e32[4 * e + 0]; g_ev[e] = e32[4 * e + 2]; }
        else        { g_eu[e] = e32[2 * e + 0]; g_ev[e] = e32[2 * e + 1]; }
    }
}

// ---------------------------------------------------------------------------
// weight prep: split fp32 -> bf16 hi/lo, transpose to [n][k]
// ---------------------------------------------------------------------------
__global__ __launch_bounds__(256) void prep_weights_kernel(
    const float* __restrict__ ew1, const float* __restrict__ ew2)
{
    const int tid = blockIdx.x * 256 + threadIdx.x;
    const int stride = gridDim.x * 256;
    for (int idx = tid; idx < 256 * 128; idx += stride) {
        const int n = idx >> 7, k = idx & 127;
        const float w = ew1[k * HID + n];
        const __nv_bfloat16 hi = __float2bfloat16_rn(w);
        g_B1bf[n * KS1 + k]       = hi;
        g_B1bf[n * KS1 + 128 + k] = __float2bfloat16_rn(w - __bfloat162float(hi));
    }
    for (int idx = tid; idx < 128 * 256; idx += stride) {
        const int n = idx >> 8, k = idx & 255;
        const float w = ew2[k * OUT + n];
        const __nv_bfloat16 hi = __float2bfloat16_rn(w);
        g_B2bf[n * KS2 + k]       = hi;
        g_B2bf[n * KS2 + 256 + k] = __float2bfloat16_rn(w - __bfloat162float(hi));
    }
    // zero pads (never read by MMA, but keep memory defined)
    for (int idx = tid; idx < 256 * 8; idx += stride)
        g_B1bf[(idx >> 3) * KS1 + 256 + (idx & 7)] = __float2bfloat16_rn(0.0f);
    for (int idx = tid; idx < 128 * 24; idx += stride)
        g_B2bf[(idx / 24) * KS2 + 512 + (idx % 24)] = __float2bfloat16_rn(0.0f);
}

// ---------------------------------------------------------------------------
// GEMM1 half: [64m x 128n x (3x128)k] -> split-store into As2
// warp tile 32m x 32n; fragments loaded manually (conflict-free strides)
// ---------------------------------------------------------------------------
static __device__ __forceinline__ void gemm1_half(
    const __nv_bfloat16* As1, const __nv_bfloat16* Bs1, __nv_bfloat16* As2,
    const float* eb1f, int wid, int lid, int H)
{
    const int g  = lid >> 2;
    const int tg = lid & 3;
    const int m0  = (wid & 1) * 32;
    const int nl0 = (wid >> 1) * 32;

    float acc[2][4][4] = {};
    #pragma unroll 1
    for (int seg = 0; seg < 3; seg++) {
        const int aoff = (seg == 1) ? 128 : 0;
        const int boff = (seg == 2) ? 128 : 0;
        #pragma unroll 2
        for (int k16 = 0; k16 < 8; k16++) {
            const int ka = aoff + k16 * 16 + tg * 2;
            const int kb = boff + k16 * 16 + tg * 2;
            uint32_t a[2][4];
            #pragma unroll
            for (int mi = 0; mi < 2; mi++) {
                const __nv_bfloat16* Ar = As1 + (m0 + mi * 16 + g) * KS1 + ka;
                a[mi][0] = *(const uint32_t*)Ar;
                a[mi][1] = *(const uint32_t*)(Ar + 8 * KS1);
                a[mi][2] = *(const uint32_t*)(Ar + 8);
                a[mi][3] = *(const uint32_t*)(Ar + 8 * KS1 + 8);
            }
            #pragma unroll
            for (int nt = 0; nt < 4; nt++) {
                const __nv_bfloat16* Br = Bs1 + (nl0 + nt * 8 + g) * KS1 + kb;
                uint32_t b[2];
                b[0] = *(const uint32_t*)Br;
                b[1] = *(const uint32_t*)(Br + 8);
                mma16816(acc[0][nt], a[0], b);
                mma16816(acc[1][nt], a[1], b);
            }
        }
    }
    // bias + relu + split-store: cols go to As2 k-position H*128 + n
    #pragma unroll
    for (int mi = 0; mi < 2; mi++) {
        const int r0 = m0 + mi * 16 + g;
        #pragma unroll
        for (int nt = 0; nt < 4; nt++) {
            const int nloc = nl0 + nt * 8 + tg * 2;
            const int ng   = H * 128 + nloc;
            const float b0 = eb1f[ng], b1 = eb1f[ng + 1];
            const float v0 = fmaxf(acc[mi][nt][0] + b0, 0.f);
            const float v1 = fmaxf(acc[mi][nt][1] + b1, 0.f);
            const float v2 = fmaxf(acc[mi][nt][2] + b0, 0.f);
            const float v3 = fmaxf(acc[mi][nt][3] + b1, 0.f);
            __nv_bfloat16* row0 = As2 + (size_t)r0 * KS2;
            __nv_bfloat16* row1 = As2 + (size_t)(r0 + 8) * KS2;
            split_store(row0 + ng, row0 + 256 + ng, v0, v1);
            split_store(row1 + ng, row1 + 256 + ng, v2, v3);
        }
    }
}

// ---------------------------------------------------------------------------
// GEMM2 half: [64m x 64n x (3x256)k] -> Dh (f32, +bias)
// warp tile 32m x 16n
// ---------------------------------------------------------------------------
static __device__ __forceinline__ void gemm2_half(
    const __nv_bfloat16* As2, const __nv_bfloat16* Bs2, float* Dh,
    const float* eb2f, int wid, int lid, int H2)
{
    const int g  = lid >> 2;
    const int tg = lid & 3;
    const int m0  = (wid & 1) * 32;
    const int nl0 = (wid >> 1) * 16;

    float acc[2][2][4] = {};
    #pragma unroll 1
    for (int seg = 0; seg < 3; seg++) {
        const int aoff = (seg == 1) ? 256 : 0;
        const int boff = (seg == 2) ? 256 : 0;
        #pragma unroll 2
        for (int k16 = 0; k16 < 16; k16++) {
            const int ka = aoff + k16 * 16 + tg * 2;
            const int kb = boff + k16 * 16 + tg * 2;
            uint32_t a[2][4];
            #pragma unroll
            for (int mi = 0; mi < 2; mi++) {
                const __nv_bfloat16* Ar = As2 + (m0 + mi * 16 + g) * KS2 + ka;
                a[mi][0] = *(const uint32_t*)Ar;
                a[mi][1] = *(const uint32_t*)(Ar + 8 * KS2);
                a[mi][2] = *(const uint32_t*)(Ar + 8);
                a[mi][3] = *(const uint32_t*)(Ar + 8 * KS2 + 8);
            }
            #pragma unroll
            for (int nt = 0; nt < 2; nt++) {
                const __nv_bfloat16* Br = Bs2 + (nl0 + nt * 8 + g) * KS2 + kb;
                uint32_t b[2];
                b[0] = *(const uint32_t*)Br;
                b[1] = *(const uint32_t*)(Br + 8);
                mma16816(acc[0][nt], a[0], b);
                mma16816(acc[1][nt], a[1], b);
            }
        }
    }
    #pragma unroll
    for (int mi = 0; mi < 2; mi++) {
        const int r0 = m0 + mi * 16 + g;
        #pragma unroll
        for (int nt = 0; nt < 2; nt++) {
            const int cl = nl0 + nt * 8 + tg * 2;
            const int ng = H2 * 64 + cl;
            float2 lo, hi2;
            lo.x  = acc[mi][nt][0] + eb2f[ng];
            lo.y  = acc[mi][nt][1] + eb2f[ng + 1];
            hi2.x = acc[mi][nt][2] + eb2f[ng];
            hi2.y = acc[mi][nt][3] + eb2f[ng + 1];
            *(float2*)&Dh[r0 * DS + cl]       = lo;
            *(float2*)&Dh[(r0 + 8) * DS + cl] = hi2;
        }
    }
}

// ---------------------------------------------------------------------------
// Edge MLP v6: mma.sync split-bf16 GEMMs + red.v4 scatter
// ---------------------------------------------------------------------------
__global__ __launch_bounds__(256, 1) void edge_mlp_tc_kernel(
    const float* __restrict__ x,
    const float* __restrict__ eb1, const float* __restrict__ eb2)
{
    extern __shared__ __align__(16) char smc[];
    __nv_bfloat16* As1 = (__nv_bfloat16*)(smc + OFF_AS1);
    __nv_bfloat16* Bs1 = (__nv_bfloat16*)(smc + OFF_BS1);
    __nv_bfloat16* As2 = (__nv_bfloat16*)(smc + OFF_AS2);
    __nv_bfloat16* Bs2 = (__nv_bfloat16*)(smc + OFF_BS2);
    float*         Dh  = (float*)(smc + OFF_DH);

    __shared__ int   us[ET_M], vs[ET_M];
    __shared__ float eb1f[HID], eb2f[OUT];

    const int t   = threadIdx.x;
    const int wid = t >> 5;
    const int lid = t & 31;
    const int e0  = blockIdx.x * ET_M;
    const int b   = blockIdx.y;
    const int count = min(ET_M, NEDGE - e0);

    if (t < ET_M) {
        const int e = min(e0 + t, NEDGE - 1);
        us[t] = g_eu[e]; vs[t] = g_ev[e];
    }
    eb1f[t] = eb1[t];
    if (t < OUT) eb2f[t] = eb2[t];
    __syncthreads();

    // gather x[u]||x[v] -> As1 split hi|lo (4096 float2)
    const float* xb = x + (size_t)b * NNODE * IN_DIM;
    #pragma unroll
    for (int it = 0; it < 16; it++) {
        const int q  = t + it * 256;
        const int m  = q >> 6;
        const int c  = (q & 63) * 2;       // col 0..126
        const int node = (c < IN_DIM) ? us[m] : vs[m];
        const float2 xv = *(const float2*)&xb[(size_t)node * IN_DIM + (c & (IN_DIM - 1))];
        __nv_bfloat16* row = As1 + m * KS1;
        split_store(row + c, row + 128 + c, xv.x, xv.y);
    }
    // copy Bs1 half 0 (67584 B)
    {
        const float4* src = (const float4*)g_B1bf;
        float4* dst = (float4*)Bs1;
        #pragma unroll 1
        for (int i = t; i < 4224; i += 256) dst[i] = src[i];
    }
    __syncthreads();

    gemm1_half(As1, Bs1, As2, eb1f, wid, lid, 0);
    __syncthreads();

    // copy Bs1 half 1
    {
        const float4* src = (const float4*)(g_B1bf + 128 * KS1);
        float4* dst = (float4*)Bs1;
        #pragma unroll 1
        for (int i = t; i < 4224; i += 256) dst[i] = src[i];
    }
    __syncthreads();

    gemm1_half(As1, Bs1, As2, eb1f, wid, lid, 1);
    __syncthreads();

    // copy Bs2 half 0 (68608 B; overwrites As1/Bs1 - now dead)
    {
        const float4* src = (const float4*)g_B2bf;
        float4* dst = (float4*)Bs2;
        #pragma unroll 1
        for (int i = t; i < 4288; i += 256) dst[i] = src[i];
    }
    __syncthreads();

    gemm2_half(As2, Bs2, Dh, eb2f, wid, lid, 0);
    __syncthreads();

    // scatter half 0 + copy Bs2 half 1
    float* Hb = g_H + (size_t)b * NNODE * OUT;
    #pragma unroll 1
    for (int i = t; i < 1024; i += 256) {
        const int m  = i >> 4;
        const int c4 = (i & 15) * 4;
        if (m < count) {
            const float4 vv = *(const float4*)&Dh[m * DS + c4];
            red_add_v4(&Hb[(size_t)us[m] * OUT + c4], vv.x, vv.y, vv.z, vv.w);
            red_add_v4(&Hb[(size_t)vs[m] * OUT + c4], vv.x, vv.y, vv.z, vv.w);
        }
    }
    {
        const float4* src = (const float4*)(g_B2bf + 64 * KS2);
        float4* dst = (float4*)Bs2;
        #pragma unroll 1
        for (int i = t; i < 4288; i += 256) dst[i] = src[i];
    }
    __syncthreads();

    gemm2_half(As2, Bs2, Dh, eb2f, wid, lid, 1);
    __syncthreads();

    // scatter half 1
    #pragma unroll 1
    for (int i = t; i < 1024; i += 256) {
        const int m  = i >> 4;
        const int c4 = (i & 15) * 4;
        if (m < count) {
            const float4 vv = *(const float4*)&Dh[m * DS + c4];
            red_add_v4(&Hb[(size_t)us[m] * OUT + 64 + c4], vv.x, vv.y, vv.z, vv.w);
            red_add_v4(&Hb[(size_t)vs[m] * OUT + 64 + c4], vv.x, vv.y, vv.z, vv.w);
        }
    }
}

// ---------------------------------------------------------------------------
// Node MLP (fp32, R7 proven)
// ---------------------------------------------------------------------------
__global__ __launch_bounds__(256, 3) void node_mlp_kernel(
    const float* __restrict__ x,
    const float* __restrict__ nw1, const float* __restrict__ nb1,
    const float* __restrict__ nw2, const float* __restrict__ nb2)
{
    extern __shared__ float sm[];
    float* xsT = sm;
    float* hs  = sm + IN_DIM * RS;
    float* ws  = hs + MPB * HS_RS;

    const int t    = threadIdx.x;
    const int base = blockIdx.x * MPB;

    #pragma unroll
    for (int i = 0; i < 2; i++) {
        const int q  = t + i * 256;
        const int m  = q >> 4;
        const int c4 = (q & 15) * 4;
        const float4 v = *(const float4*)&x[(size_t)(base + m) * IN_DIM + c4];
        xsT[(c4 + 0) * RS + m] = v.x;
        xsT[(c4 + 1) * RS + m] = v.y;
        xsT[(c4 + 2) * RS + m] = v.z;
        xsT[(c4 + 3) * RS + m] = v.w;
    }

    {
        const int m0 = (t >> 6) * 8;
        const int n0 = (t & 63) * 4;
        const float4 b1 = *(const float4*)&nb1[n0];
        float acc[8][4];
        #pragma unroll
        for (int i = 0; i < 8; i++) {
            acc[i][0] = b1.x; acc[i][1] = b1.y; acc[i][2] = b1.z; acc[i][3] = b1.w;
        }
        #pragma unroll 1
        for (int kc = 0; kc < IN_DIM / 16; kc++) {
            __syncthreads();
            {
                const float4* src = (const float4*)(nw1 + kc * 16 * HID);
                float4* dst = (float4*)ws;
                #pragma unroll
                for (int j = 0; j < 4; j++) dst[t + j * 256] = src[t + j * 256];
            }
            __syncthreads();
            const float* aT = xsT + kc * 16 * RS;
            #pragma unroll 4
            for (int k = 0; k < 16; k++) {
                const float4 bv = *(const float4*)&ws[k * HID + n0];
                const float4 a0 = *(const float4*)&aT[k * RS + m0];
                const float4 a1 = *(const float4*)&aT[k * RS + m0 + 4];
                acc[0][0] = fmaf(a0.x, bv.x, acc[0][0]); acc[0][1] = fmaf(a0.x, bv.y, acc[0][1]);
                acc[0][2] = fmaf(a0.x, bv.z, acc[0][2]); acc[0][3] = fmaf(a0.x, bv.w, acc[0][3]);
                acc[1][0] = fmaf(a0.y, bv.x, acc[1][0]); acc[1][1] = fmaf(a0.y, bv.y, acc[1][1]);
                acc[1][2] = fmaf(a0.y, bv.z, acc[1][2]); acc[1][3] = fmaf(a0.y, bv.w, acc[1][3]);
                acc[2][0] = fmaf(a0.z, bv.x, acc[2][0]); acc[2][1] = fmaf(a0.z, bv.y, acc[2][1]);
                acc[2][2] = fmaf(a0.z, bv.z, acc[2][2]); acc[2][3] = fmaf(a0.z, bv.w, acc[2][3]);
                acc[3][0] = fmaf(a0.w, bv.x, acc[3][0]); acc[3][1] = fmaf(a0.w, bv.y, acc[3][1]);
                acc[3][2] = fmaf(a0.w, bv.z, acc[3][2]); acc[3][3] = fmaf(a0.w, bv.w, acc[3][3]);
                acc[4][0] = fmaf(a1.x, bv.x, acc[4][0]); acc[4][1] = fmaf(a1.x, bv.y, acc[4][1]);
                acc[4][2] = fmaf(a1.x, bv.z, acc[4][2]); acc[4][3] = fmaf(a1.x, bv.w, acc[4][3]);
                acc[5][0] = fmaf(a1.y, bv.x, acc[5][0]); acc[5][1] = fmaf(a1.y, bv.y, acc[5][1]);
                acc[5][2] = fmaf(a1.y, bv.z, acc[5][2]); acc[5][3] = fmaf(a1.y, bv.w, acc[5][3]);
                acc[6][0] = fmaf(a1.z, bv.x, acc[6][0]); acc[6][1] = fmaf(a1.z, bv.y, acc[6][1]);
                acc[6][2] = fmaf(a1.z, bv.z, acc[6][2]); acc[6][3] = fmaf(a1.z, bv.w, acc[6][3]);
                acc[7][0] = fmaf(a1.w, bv.x, acc[7][0]); acc[7][1] = fmaf(a1.w, bv.y, acc[7][1]);
                acc[7][2] = fmaf(a1.w, bv.z, acc[7][2]); acc[7][3] = fmaf(a1.w, bv.w, acc[7][3]);
            }
        }
        #pragma unroll
        for (int i = 0; i < 8; i++) {
            float4 r = make_float4(fmaxf(acc[i][0], 0.f), fmaxf(acc[i][1], 0.f),
                                   fmaxf(acc[i][2], 0.f), fmaxf(acc[i][3], 0.f));
            *(float4*)&hs[(m0 + i) * HS_RS + n0] = r;
        }
    }

    {
        const int m0 = (t >> 5) * 4;
        const int n0 = (t & 31) * 4;
        const float4 b2 = *(const float4*)&nb2[n0];
        float acc[4][4];
        #pragma unroll
        for (int i = 0; i < 4; i++) {
            acc[i][0] = b2.x; acc[i][1] = b2.y; acc[i][2] = b2.z; acc[i][3] = b2.w;
        }
        #pragma unroll 1
        for (int kc = 0; kc < HID / 32; kc++) {
            __syncthreads();
            {
                const float4* src = (const float4*)(nw2 + kc * 32 * OUT);
                float4* dst = (float4*)ws;
                #pragma unroll
                for (int j = 0; j < 4; j++) dst[t + j * 256] = src[t + j * 256];
            }
            __syncthreads();
            #pragma unroll 2
            for (int k4 = 0; k4 < 32; k4 += 4) {
                const float4 b0  = *(const float4*)&ws[(k4 + 0) * OUT + n0];
                const float4 b1v = *(const float4*)&ws[(k4 + 1) * OUT + n0];
                const float4 b2v = *(const float4*)&ws[(k4 + 2) * OUT + n0];
                const float4 b3v = *(const float4*)&ws[(k4 + 3) * OUT + n0];
                #pragma unroll
                for (int i = 0; i < 4; i++) {
                    const float4 a = *(const float4*)&hs[(m0 + i) * HS_RS + kc * 32 + k4];
                    acc[i][0] = fmaf(a.x, b0.x,  acc[i][0]);
                    acc[i][1] = fmaf(a.x, b0.y,  acc[i][1]);
                    acc[i][2] = fmaf(a.x, b0.z,  acc[i][2]);
                    acc[i][3] = fmaf(a.x, b0.w,  acc[i][3]);
                    acc[i][0] = fmaf(a.y, b1v.x, acc[i][0]);
                    acc[i][1] = fmaf(a.y, b1v.y, acc[i][1]);
                    acc[i][2] = fmaf(a.y, b1v.z, acc[i][2]);
                    acc[i][3] = fmaf(a.y, b1v.w, acc[i][3]);
                    acc[i][0] = fmaf(a.z, b2v.x, acc[i][0]);
                    acc[i][1] = fmaf(a.z, b2v.y, acc[i][1]);
                    acc[i][2] = fmaf(a.z, b2v.z, acc[i][2]);
                    acc[i][3] = fmaf(a.z, b2v.w, acc[i][3]);
                    acc[i][0] = fmaf(a.w, b3v.x, acc[i][0]);
                    acc[i][1] = fmaf(a.w, b3v.y, acc[i][1]);
                    acc[i][2] = fmaf(a.w, b3v.z, acc[i][2]);
                    acc[i][3] = fmaf(a.w, b3v.w, acc[i][3]);
                }
            }
        }
        #pragma unroll
        for (int i = 0; i < 4; i++)
            *(float4*)&g_H[(size_t)(base + m0 + i) * OUT + n0] =
                make_float4(acc[i][0], acc[i][1], acc[i][2], acc[i][3]);
    }
}

// ---------------------------------------------------------------------------
// decode: out = H @ dw + db (unchanged)
// ---------------------------------------------------------------------------
__global__ __launch_bounds__(256) void decode_kernel(
    const float* __restrict__ dw, const float* __restrict__ db,
    float* __restrict__ out)
{
    __shared__ __align__(16) float hsm[DPB][OUT];

    const int base = blockIdx.x * DPB;
    const int t = threadIdx.x;

    for (int i = t; i < DPB * OUT; i += 256)
        hsm[i / OUT][i % OUT] = g_H[(size_t)base * OUT + i];
    __syncthreads();

    const int o   = t & (IN_DIM - 1);
    const int nb0 = (t >> 6) * (DPB / 4);
    float acc[DPB / 4];
    {
        const float bb = db[o];
        #pragma unroll
        for (int n = 0; n < DPB / 4; n++) acc[n] = bb;
    }
    #pragma unroll 4
    for (int k = 0; k < OUT; k += 4) {
        const float w0 = dw[(k + 0) * IN_DIM + o];
        const float w1 = dw[(k + 1) * IN_DIM + o];
        const float w2 = dw[(k + 2) * IN_DIM + o];
        const float w3 = dw[(k + 3) * IN_DIM + o];
        #pragma unroll
        for (int n = 0; n < DPB / 4; n++) {
            float4 v = *reinterpret_cast<const float4*>(&hsm[nb0 + n][k]);
            acc[n] = fmaf(v.x, w0, acc[n]);
            acc[n] = fmaf(v.y, w1, acc[n]);
            acc[n] = fmaf(v.z, w2, acc[n]);
            acc[n] = fmaf(v.w, w3, acc[n]);
        }
    }
    #pragma unroll
    for (int n = 0; n < DPB / 4; n++)
        out[(size_t)(base + nb0 + n) * IN_DIM + o] = acc[n];
}

// ---------------------------------------------------------------------------
extern "C" void kernel_launch(void* const* d_in, const int* in_sizes, int n_in,
                              void* d_out, int out_size)
{
    const float* x   = (const float*)d_in[0];
    const int*   e32 = (const int*)d_in[1];
    const float* ew1 = (const float*)d_in[2];
    const float* eb1 = (const float*)d_in[3];
    const float* ew2 = (const float*)d_in[4];
    const float* eb2 = (const float*)d_in[5];
    const float* nw1 = (const float*)d_in[6];
    const float* nb1 = (const float*)d_in[7];
    const float* nw2 = (const float*)d_in[8];
    const float* nb2 = (const float*)d_in[9];
    const float* dw  = (const float*)d_in[10];
    const float* db  = (const float*)d_in[11];
    float*       out = (float*)d_out;

    const int node_smem = (IN_DIM * RS + MPB * HS_RS + 16 * HID) * (int)sizeof(float); // 58880

    static bool attr_done = false;
    if (!attr_done) {
        cudaFuncSetAttribute(edge_mlp_tc_kernel,
            cudaFuncAttributeMaxDynamicSharedMemorySize, EDGE_DSMEM);
        cudaFuncSetAttribute(node_mlp_kernel,
            cudaFuncAttributeMaxDynamicSharedMemorySize, node_smem);
        attr_done = true;
    }

    detect_edge_dtype_kernel<<<1, 32>>>(e32);
    convert_edges_kernel<<<(NEDGE + 255) / 256, 256>>>(e32);
    prep_weights_kernel<<<128, 256>>>(ew1, ew2);

    node_mlp_kernel<<<TOTAL_NODES / MPB, 256, node_smem>>>(x, nw1, nb1, nw2, nb2);

    dim3 egrid((NEDGE + ET_M - 1) / ET_M, B);
    edge_mlp_tc_kernel<<<egrid, 256, EDGE_DSMEM>>>(x, eb1, eb2);

    decode_kernel<<<TOTAL_NODES / DPB, 256>>>(dw, db, out);
}

// round 10
// speedup vs baseline: 2.4859x; 1.3792x over previous
#include <cuda_runtime.h>
#include <cuda_bf16.h>
#include <cstdint>

#define B      2
#define NNODE  50000
#define IN_DIM 64
#define HID    256
#define OUT    128
#define NEDGE  500000
#define TOTAL_NODES (B * NNODE)

// fp32 node/decode tiles (proven R7 config)
#define MPB 32
#define DPB 16
#define RS  36
#define HS_RS (HID + 4)

// edge tensor kernel: 64 edges x 2 batches = 128 M-rows per block
#define KS1  264     // A1/B1 row stride (bf16): 128 hi + 128 lo + 8 pad
#define KS2  520     // A2/B2 row stride (bf16): 256 hi + 256 lo + 8 pad
#define DHS  68      // Dh row stride (f32)
// dynamic smem offsets (bytes)
#define OFF_A1  0        // 128*264*2 = 67584
#define OFF_B1  67584    // 256*264*2 = 135168 -> ends 202752
#define OFF_A2  0        // 128*520*2 = 133120 (overlays A1+B1 after GEMM1)
#define OFF_B2  133120   // 64*520*2  = 66560  -> ends 199680
#define OFF_DH  199680   // 64*68*4   = 17408  -> ends 217088
#define EDGE_DSMEM 217088

// ---------------------------------------------------------------------------
// device globals (allocation-guard-safe)
// ---------------------------------------------------------------------------
__device__ float g_H[(size_t)B * NNODE * OUT];
__device__ int   g_eu[NEDGE];
__device__ int   g_ev[NEDGE];
__device__ int   g_is64;
// pre-split, pre-transposed bf16 weight images [n][k']:
__device__ __align__(16) __nv_bfloat16 g_B1bf[256 * KS1]; // ew1: hi at k, lo at 128+k
__device__ __align__(16) __nv_bfloat16 g_B2bf[128 * KS2]; // ew2: hi at k, lo at 256+k

// ---------------------------------------------------------------------------
// helpers
// ---------------------------------------------------------------------------
static __device__ __forceinline__ void mma16816(float* d, const uint32_t* a, const uint32_t* b)
{
    asm volatile(
        "mma.sync.aligned.m16n8k16.row.col.f32.bf16.bf16.f32 "
        "{%0,%1,%2,%3}, {%4,%5,%6,%7}, {%8,%9}, {%0,%1,%2,%3};"
        : "+f"(d[0]), "+f"(d[1]), "+f"(d[2]), "+f"(d[3])
        : "r"(a[0]), "r"(a[1]), "r"(a[2]), "r"(a[3]), "r"(b[0]), "r"(b[1]));
}

static __device__ __forceinline__ void red_add_v4(float* p, float a, float b, float c, float d)
{
    asm volatile("red.global.add.v4.f32 [%0], {%1, %2, %3, %4};"
                 :: "l"(p), "f"(a), "f"(b), "f"(c), "f"(d) : "memory");
}

static __device__ __forceinline__ void split_store(__nv_bfloat16* hi_p, __nv_bfloat16* lo_p,
                                                   float v0, float v1)
{
    __nv_bfloat162 hp = __floats2bfloat162_rn(v0, v1);
    const float h0 = __bfloat162float(hp.x), h1 = __bfloat162float(hp.y);
    __nv_bfloat162 lp = __floats2bfloat162_rn(v0 - h0, v1 - h1);
    *(uint32_t*)hi_p = *(const uint32_t*)&hp;
    *(uint32_t*)lo_p = *(const uint32_t*)&lp;
}

// ---------------------------------------------------------------------------
// edge dtype detect + SoA normalize (proven)
// ---------------------------------------------------------------------------
__global__ void detect_edge_dtype_kernel(const int* __restrict__ e32)
{
    if (threadIdx.x == 0 && blockIdx.x == 0) {
        int all_zero = 1;
        #pragma unroll 1
        for (int i = 1; i < 256; i += 2)
            if (e32[i] != 0) { all_zero = 0; break; }
        g_is64 = all_zero;
    }
}

__global__ __launch_bounds__(256) void convert_edges_kernel(const int* __restrict__ e32)
{
    const int e = blockIdx.x * 256 + threadIdx.x;
    if (e < NEDGE) {
        if (g_is64) { g_eu[e] = e32[4 * e + 0]; g_ev[e] = e32[4 * e + 2]; }
        else        { g_eu[e] = e32[2 * e + 0]; g_ev[e] = e32[2 * e + 1]; }
    }
}

// ---------------------------------------------------------------------------
// weight prep: split fp32 -> bf16 hi/lo, transpose to [n][k]
// ---------------------------------------------------------------------------
__global__ __launch_bounds__(256) void prep_weights_kernel(
    const float* __restrict__ ew1, const float* __restrict__ ew2)
{
    const int tid = blockIdx.x * 256 + threadIdx.x;
    const int stride = gridDim.x * 256;
    for (int idx = tid; idx < 256 * 128; idx += stride) {
        const int n = idx >> 7, k = idx & 127;
        const float w = ew1[k * HID + n];
        const __nv_bfloat16 hi = __float2bfloat16_rn(w);
        g_B1bf[n * KS1 + k]       = hi;
        g_B1bf[n * KS1 + 128 + k] = __float2bfloat16_rn(w - __bfloat162float(hi));
    }
    for (int idx = tid; idx < 128 * 256; idx += stride) {
        const int n = idx >> 8, k = idx & 255;
        const float w = ew2[k * OUT + n];
        const __nv_bfloat16 hi = __float2bfloat16_rn(w);
        g_B2bf[n * KS2 + k]       = hi;
        g_B2bf[n * KS2 + 256 + k] = __float2bfloat16_rn(w - __bfloat162float(hi));
    }
}

// ---------------------------------------------------------------------------
// Edge MLP v7: 64 edges x BOTH batches per block; split-bf16 mma.sync.
// ---------------------------------------------------------------------------
__global__ __launch_bounds__(256, 1) void edge_mlp_tc_kernel(
    const float* __restrict__ x,
    const float* __restrict__ eb1, const float* __restrict__ eb2)
{
    extern __shared__ __align__(16) char smc[];
    __nv_bfloat16* A1 = (__nv_bfloat16*)(smc + OFF_A1);
    __nv_bfloat16* B1 = (__nv_bfloat16*)(smc + OFF_B1);
    __nv_bfloat16* A2 = (__nv_bfloat16*)(smc + OFF_A2);
    __nv_bfloat16* B2 = (__nv_bfloat16*)(smc + OFF_B2);
    float*         Dh = (float*)(smc + OFF_DH);

    __shared__ int   us[64], vs[64];
    __shared__ float eb1f[HID], eb2f[OUT];

    const int t   = threadIdx.x;
    const int wid = t >> 5;
    const int lid = t & 31;
    const int g   = lid >> 2;
    const int tg  = lid & 3;
    const int e0  = blockIdx.x * 64;
    const int count = min(64, NEDGE - e0);

    if (t < 64) {
        const int e = min(e0 + t, NEDGE - 1);
        us[t] = g_eu[e]; vs[t] = g_ev[e];
    }
    eb1f[t] = eb1[t];
    if (t < OUT) eb2f[t] = eb2[t];
    __syncthreads();

    // gather: rows 0-63 batch0, 64-127 batch1; split hi|lo into A1
    #pragma unroll
    for (int it = 0; it < 32; it++) {
        const int q = t + it * 256;                   // 8192 float2
        const int m = q >> 6;
        const int c = (q & 63) * 2;
        const int node = (c < IN_DIM) ? us[m & 63] : vs[m & 63];
        const float2 xv = *(const float2*)
            &x[((size_t)(m >> 6) * NNODE + node) * IN_DIM + (c & (IN_DIM - 1))];
        split_store(A1 + m * KS1 + c, A1 + m * KS1 + 128 + c, xv.x, xv.y);
    }
    // copy B1 (all 256 n-rows, 135168 B)
    {
        const float4* src = (const float4*)g_B1bf;
        float4* dst = (float4*)B1;
        #pragma unroll 1
        for (int i = t; i < 8448; i += 256) dst[i] = src[i];
    }
    __syncthreads();

    // ---- GEMM1: warp tile 64m x 32n, both 128-n halves (A frags reused) ----
    const int m1 = (wid >> 2) * 64;
    const int n1 = (wid & 3) * 32;
    float acc1[2][4][4][4] = {};
    #pragma unroll 1
    for (int seg = 0; seg < 3; seg++) {
        const int aoff = (seg == 1) ? 128 : 0;
        const int boff = (seg == 2) ? 128 : 0;
        #pragma unroll 2
        for (int k16 = 0; k16 < 8; k16++) {
            const int ka = aoff + k16 * 16 + tg * 2;
            const int kb = boff + k16 * 16 + tg * 2;
            uint32_t a[4][4];
            #pragma unroll
            for (int mi = 0; mi < 4; mi++) {
                const __nv_bfloat16* Ar = A1 + (m1 + mi * 16 + g) * KS1 + ka;
                a[mi][0] = *(const uint32_t*)Ar;
                a[mi][1] = *(const uint32_t*)(Ar + 8 * KS1);
                a[mi][2] = *(const uint32_t*)(Ar + 8);
                a[mi][3] = *(const uint32_t*)(Ar + 8 * KS1 + 8);
            }
            #pragma unroll
            for (int h = 0; h < 2; h++) {
                #pragma unroll
                for (int nt = 0; nt < 4; nt++) {
                    const __nv_bfloat16* Br = B1 + (h * 128 + n1 + nt * 8 + g) * KS1 + kb;
                    uint32_t b[2];
                    b[0] = *(const uint32_t*)Br;
                    b[1] = *(const uint32_t*)(Br + 8);
                    #pragma unroll
                    for (int mi = 0; mi < 4; mi++)
                        mma16816(acc1[h][mi][nt], a[mi], b);
                }
            }
        }
    }
    __syncthreads();   // all GEMM1 reads done; A2 overlays A1+B1

    // epilogue G1: bias + relu + split -> A2 [128m][256hi|256lo]
    #pragma unroll
    for (int h = 0; h < 2; h++) {
        #pragma unroll
        for (int mi = 0; mi < 4; mi++) {
            const int r0 = m1 + mi * 16 + g;
            #pragma unroll
            for (int nt = 0; nt < 4; nt++) {
                const int c = h * 128 + n1 + nt * 8 + tg * 2;
                const float b0 = eb1f[c], b1 = eb1f[c + 1];
                const float v0 = fmaxf(acc1[h][mi][nt][0] + b0, 0.f);
                const float v1 = fmaxf(acc1[h][mi][nt][1] + b1, 0.f);
                const float v2 = fmaxf(acc1[h][mi][nt][2] + b0, 0.f);
                const float v3 = fmaxf(acc1[h][mi][nt][3] + b1, 0.f);
                __nv_bfloat16* r0p = A2 + (size_t)r0 * KS2;
                __nv_bfloat16* r1p = A2 + (size_t)(r0 + 8) * KS2;
                split_store(r0p + c, r0p + 256 + c, v0, v1);
                split_store(r1p + c, r1p + 256 + c, v2, v3);
            }
        }
    }
    __syncthreads();

    // ---- GEMM2: two 64-n halves; warp tile 32m x 32n ----
    const int m2 = (wid >> 1) * 32;
    const int n2 = (wid & 1) * 32;
    #pragma unroll 1
    for (int h2 = 0; h2 < 2; h2++) {
        // copy B2 half (66560 B)
        {
            const float4* src = (const float4*)(g_B2bf + (size_t)h2 * 64 * KS2);
            float4* dst = (float4*)B2;
            #pragma unroll 1
            for (int i = t; i < 4160; i += 256) dst[i] = src[i];
        }
        __syncthreads();

        float acc2[2][4][4] = {};
        #pragma unroll 1
        for (int seg = 0; seg < 3; seg++) {
            const int aoff = (seg == 1) ? 256 : 0;
            const int boff = (seg == 2) ? 256 : 0;
            #pragma unroll 2
            for (int k16 = 0; k16 < 16; k16++) {
                const int ka = aoff + k16 * 16 + tg * 2;
                const int kb = boff + k16 * 16 + tg * 2;
                uint32_t a[2][4];
                #pragma unroll
                for (int mi = 0; mi < 2; mi++) {
                    const __nv_bfloat16* Ar = A2 + (m2 + mi * 16 + g) * KS2 + ka;
                    a[mi][0] = *(const uint32_t*)Ar;
                    a[mi][1] = *(const uint32_t*)(Ar + 8 * KS2);
                    a[mi][2] = *(const uint32_t*)(Ar + 8);
                    a[mi][3] = *(const uint32_t*)(Ar + 8 * KS2 + 8);
                }
                #pragma unroll
                for (int nt = 0; nt < 4; nt++) {
                    const __nv_bfloat16* Br = B2 + (n2 + nt * 8 + g) * KS2 + kb;
                    uint32_t b[2];
                    b[0] = *(const uint32_t*)Br;
                    b[1] = *(const uint32_t*)(Br + 8);
                    mma16816(acc2[0][nt], a[0], b);
                    mma16816(acc2[1][nt], a[1], b);
                }
            }
        }
        __syncthreads();   // GEMM2 reads done (B2 reusable, Dh phases next)

        // scatter in 2 phases of 64 m-rows (phase pg == batch pg)
        #pragma unroll 1
        for (int pg = 0; pg < 2; pg++) {
            if ((wid >> 2) == pg) {     // warps owning m in [pg*64, pg*64+64)
                #pragma unroll
                for (int mi = 0; mi < 2; mi++) {
                    const int r = m2 + mi * 16 + g - pg * 64;
                    #pragma unroll
                    for (int nt = 0; nt < 4; nt++) {
                        const int cc = n2 + nt * 8 + tg * 2;
                        const float b0 = eb2f[h2 * 64 + cc];
                        const float b1 = eb2f[h2 * 64 + cc + 1];
                        float2 lo, hi;
                        lo.x = acc2[mi][nt][0] + b0;
                        lo.y = acc2[mi][nt][1] + b1;
                        hi.x = acc2[mi][nt][2] + b0;
                        hi.y = acc2[mi][nt][3] + b1;
                        *(float2*)&Dh[r * DHS + cc]       = lo;
                        *(float2*)&Dh[(r + 8) * DHS + cc] = hi;
                    }
                }
            }
            __syncthreads();
            float* Hb = g_H + (size_t)pg * NNODE * OUT;
            #pragma unroll 1
            for (int i = t; i < 1024; i += 256) {
                const int r  = i >> 4;
                const int c4 = (i & 15) * 4;
                if (r < count) {
                    const float4 vv = *(const float4*)&Dh[r * DHS + c4];
                    red_add_v4(&Hb[(size_t)us[r] * OUT + h2 * 64 + c4], vv.x, vv.y, vv.z, vv.w);
                    red_add_v4(&Hb[(size_t)vs[r] * OUT + h2 * 64 + c4], vv.x, vv.y, vv.z, vv.w);
                }
            }
            __syncthreads();
        }
    }
}

// ---------------------------------------------------------------------------
// Node MLP (fp32, R7 proven)
// ---------------------------------------------------------------------------
__global__ __launch_bounds__(256, 3) void node_mlp_kernel(
    const float* __restrict__ x,
    const float* __restrict__ nw1, const float* __restrict__ nb1,
    const float* __restrict__ nw2, const float* __restrict__ nb2)
{
    extern __shared__ float sm[];
    float* xsT = sm;
    float* hs  = sm + IN_DIM * RS;
    float* ws  = hs + MPB * HS_RS;

    const int t    = threadIdx.x;
    const int base = blockIdx.x * MPB;

    #pragma unroll
    for (int i = 0; i < 2; i++) {
        const int q  = t + i * 256;
        const int m  = q >> 4;
        const int c4 = (q & 15) * 4;
        const float4 v = *(const float4*)&x[(size_t)(base + m) * IN_DIM + c4];
        xsT[(c4 + 0) * RS + m] = v.x;
        xsT[(c4 + 1) * RS + m] = v.y;
        xsT[(c4 + 2) * RS + m] = v.z;
        xsT[(c4 + 3) * RS + m] = v.w;
    }

    {
        const int m0 = (t >> 6) * 8;
        const int n0 = (t & 63) * 4;
        const float4 b1 = *(const float4*)&nb1[n0];
        float acc[8][4];
        #pragma unroll
        for (int i = 0; i < 8; i++) {
            acc[i][0] = b1.x; acc[i][1] = b1.y; acc[i][2] = b1.z; acc[i][3] = b1.w;
        }
        #pragma unroll 1
        for (int kc = 0; kc < IN_DIM / 16; kc++) {
            __syncthreads();
            {
                const float4* src = (const float4*)(nw1 + kc * 16 * HID);
                float4* dst = (float4*)ws;
                #pragma unroll
                for (int j = 0; j < 4; j++) dst[t + j * 256] = src[t + j * 256];
            }
            __syncthreads();
            const float* aT = xsT + kc * 16 * RS;
            #pragma unroll 4
            for (int k = 0; k < 16; k++) {
                const float4 bv = *(const float4*)&ws[k * HID + n0];
                const float4 a0 = *(const float4*)&aT[k * RS + m0];
                const float4 a1 = *(const float4*)&aT[k * RS + m0 + 4];
                acc[0][0] = fmaf(a0.x, bv.x, acc[0][0]); acc[0][1] = fmaf(a0.x, bv.y, acc[0][1]);
                acc[0][2] = fmaf(a0.x, bv.z, acc[0][2]); acc[0][3] = fmaf(a0.x, bv.w, acc[0][3]);
                acc[1][0] = fmaf(a0.y, bv.x, acc[1][0]); acc[1][1] = fmaf(a0.y, bv.y, acc[1][1]);
                acc[1][2] = fmaf(a0.y, bv.z, acc[1][2]); acc[1][3] = fmaf(a0.y, bv.w, acc[1][3]);
                acc[2][0] = fmaf(a0.z, bv.x, acc[2][0]); acc[2][1] = fmaf(a0.z, bv.y, acc[2][1]);
                acc[2][2] = fmaf(a0.z, bv.z, acc[2][2]); acc[2][3] = fmaf(a0.z, bv.w, acc[2][3]);
                acc[3][0] = fmaf(a0.w, bv.x, acc[3][0]); acc[3][1] = fmaf(a0.w, bv.y, acc[3][1]);
                acc[3][2] = fmaf(a0.w, bv.z, acc[3][2]); acc[3][3] = fmaf(a0.w, bv.w, acc[3][3]);
                acc[4][0] = fmaf(a1.x, bv.x, acc[4][0]); acc[4][1] = fmaf(a1.x, bv.y, acc[4][1]);
                acc[4][2] = fmaf(a1.x, bv.z, acc[4][2]); acc[4][3] = fmaf(a1.x, bv.w, acc[4][3]);
                acc[5][0] = fmaf(a1.y, bv.x, acc[5][0]); acc[5][1] = fmaf(a1.y, bv.y, acc[5][1]);
                acc[5][2] = fmaf(a1.y, bv.z, acc[5][2]); acc[5][3] = fmaf(a1.y, bv.w, acc[5][3]);
                acc[6][0] = fmaf(a1.z, bv.x, acc[6][0]); acc[6][1] = fmaf(a1.z, bv.y, acc[6][1]);
                acc[6][2] = fmaf(a1.z, bv.z, acc[6][2]); acc[6][3] = fmaf(a1.z, bv.w, acc[6][3]);
                acc[7][0] = fmaf(a1.w, bv.x, acc[7][0]); acc[7][1] = fmaf(a1.w, bv.y, acc[7][1]);
                acc[7][2] = fmaf(a1.w, bv.z, acc[7][2]); acc[7][3] = fmaf(a1.w, bv.w, acc[7][3]);
            }
        }
        #pragma unroll
        for (int i = 0; i < 8; i++) {
            float4 r = make_float4(fmaxf(acc[i][0], 0.f), fmaxf(acc[i][1], 0.f),
                                   fmaxf(acc[i][2], 0.f), fmaxf(acc[i][3], 0.f));
            *(float4*)&hs[(m0 + i) * HS_RS + n0] = r;
        }
    }

    {
        const int m0 = (t >> 5) * 4;
        const int n0 = (t & 31) * 4;
        const float4 b2 = *(const float4*)&nb2[n0];
        float acc[4][4];
        #pragma unroll
        for (int i = 0; i < 4; i++) {
            acc[i][0] = b2.x; acc[i][1] = b2.y; acc[i][2] = b2.z; acc[i][3] = b2.w;
        }
        #pragma unroll 1
        for (int kc = 0; kc < HID / 32; kc++) {
            __syncthreads();
            {
                const float4* src = (const float4*)(nw2 + kc * 32 * OUT);
                float4* dst = (float4*)ws;
                #pragma unroll
                for (int j = 0; j < 4; j++) dst[t + j * 256] = src[t + j * 256];
            }
            __syncthreads();
            #pragma unroll 2
            for (int k4 = 0; k4 < 32; k4 += 4) {
                const float4 b0  = *(const float4*)&ws[(k4 + 0) * OUT + n0];
                const float4 b1v = *(const float4*)&ws[(k4 + 1) * OUT + n0];
                const float4 b2v = *(const float4*)&ws[(k4 + 2) * OUT + n0];
                const float4 b3v = *(const float4*)&ws[(k4 + 3) * OUT + n0];
                #pragma unroll
                for (int i = 0; i < 4; i++) {
                    const float4 a = *(const float4*)&hs[(m0 + i) * HS_RS + kc * 32 + k4];
                    acc[i][0] = fmaf(a.x, b0.x,  acc[i][0]);
                    acc[i][1] = fmaf(a.x, b0.y,  acc[i][1]);
                    acc[i][2] = fmaf(a.x, b0.z,  acc[i][2]);
                    acc[i][3] = fmaf(a.x, b0.w,  acc[i][3]);
                    acc[i][0] = fmaf(a.y, b1v.x, acc[i][0]);
                    acc[i][1] = fmaf(a.y, b1v.y, acc[i][1]);
                    acc[i][2] = fmaf(a.y, b1v.z, acc[i][2]);
                    acc[i][3] = fmaf(a.y, b1v.w, acc[i][3]);
                    acc[i][0] = fmaf(a.z, b2v.x, acc[i][0]);
                    acc[i][1] = fmaf(a.z, b2v.y, acc[i][1]);
                    acc[i][2] = fmaf(a.z, b2v.z, acc[i][2]);
                    acc[i][3] = fmaf(a.z, b2v.w, acc[i][3]);
                    acc[i][0] = fmaf(a.w, b3v.x, acc[i][0]);
                    acc[i][1] = fmaf(a.w, b3v.y, acc[i][1]);
                    acc[i][2] = fmaf(a.w, b3v.z, acc[i][2]);
                    acc[i][3] = fmaf(a.w, b3v.w, acc[i][3]);
                }
            }
        }
        #pragma unroll
        for (int i = 0; i < 4; i++)
            *(float4*)&g_H[(size_t)(base + m0 + i) * OUT + n0] =
                make_float4(acc[i][0], acc[i][1], acc[i][2], acc[i][3]);
    }
}

// ---------------------------------------------------------------------------
// decode: out = H @ dw + db (unchanged)
// ---------------------------------------------------------------------------
__global__ __launch_bounds__(256) void decode_kernel(
    const float* __restrict__ dw, const float* __restrict__ db,
    float* __restrict__ out)
{
    __shared__ __align__(16) float hsm[DPB][OUT];

    const int base = blockIdx.x * DPB;
    const int t = threadIdx.x;

    for (int i = t; i < DPB * OUT; i += 256)
        hsm[i / OUT][i % OUT] = g_H[(size_t)base * OUT + i];
    __syncthreads();

    const int o   = t & (IN_DIM - 1);
    const int nb0 = (t >> 6) * (DPB / 4);
    float acc[DPB / 4];
    {
        const float bb = db[o];
        #pragma unroll
        for (int n = 0; n < DPB / 4; n++) acc[n] = bb;
    }
    #pragma unroll 4
    for (int k = 0; k < OUT; k += 4) {
        const float w0 = dw[(k + 0) * IN_DIM + o];
        const float w1 = dw[(k + 1) * IN_DIM + o];
        const float w2 = dw[(k + 2) * IN_DIM + o];
        const float w3 = dw[(k + 3) * IN_DIM + o];
        #pragma unroll
        for (int n = 0; n < DPB / 4; n++) {
            float4 v = *reinterpret_cast<const float4*>(&hsm[nb0 + n][k]);
            acc[n] = fmaf(v.x, w0, acc[n]);
            acc[n] = fmaf(v.y, w1, acc[n]);
            acc[n] = fmaf(v.z, w2, acc[n]);
            acc[n] = fmaf(v.w, w3, acc[n]);
        }
    }
    #pragma unroll
    for (int n = 0; n < DPB / 4; n++)
        out[(size_t)(base + nb0 + n) * IN_DIM + o] = acc[n];
}

// ---------------------------------------------------------------------------
extern "C" void kernel_launch(void* const* d_in, const int* in_sizes, int n_in,
                              void* d_out, int out_size)
{
    const float* x   = (const float*)d_in[0];
    const int*   e32 = (const int*)d_in[1];
    const float* ew1 = (const float*)d_in[2];
    const float* eb1 = (const float*)d_in[3];
    const float* ew2 = (const float*)d_in[4];
    const float* eb2 = (const float*)d_in[5];
    const float* nw1 = (const float*)d_in[6];
    const float* nb1 = (const float*)d_in[7];
    const float* nw2 = (const float*)d_in[8];
    const float* nb2 = (const float*)d_in[9];
    const float* dw  = (const float*)d_in[10];
    const float* db  = (const float*)d_in[11];
    float*       out = (float*)d_out;

    const int node_smem = (IN_DIM * RS + MPB * HS_RS + 16 * HID) * (int)sizeof(float); // 58880

    static bool attr_done = false;
    if (!attr_done) {
        cudaFuncSetAttribute(edge_mlp_tc_kernel,
            cudaFuncAttributeMaxDynamicSharedMemorySize, EDGE_DSMEM);
        cudaFuncSetAttribute(node_mlp_kernel,
            cudaFuncAttributeMaxDynamicSharedMemorySize, node_smem);
        attr_done = true;
    }

    detect_edge_dtype_kernel<<<1, 32>>>(e32);
    convert_edges_kernel<<<(NEDGE + 255) / 256, 256>>>(e32);
    prep_weights_kernel<<<128, 256>>>(ew1, ew2);

    node_mlp_kernel<<<TOTAL_NODES / MPB, 256, node_smem>>>(x, nw1, nb1, nw2, nb2);

    edge_mlp_tc_kernel<<<(NEDGE + 63) / 64, 256, EDGE_DSMEM>>>(x, eb1, eb2);

    decode_kernel<<<TOTAL_NODES / DPB, 256>>>(dw, db, out);
}

// round 12
// speedup vs baseline: 3.3758x; 1.3580x over previous
#include <cuda_runtime.h>
#include <cuda_bf16.h>
#include <cstdint>

#define B      2
#define NNODE  50000
#define IN_DIM 64
#define HID    256
#define OUT    128
#define NEDGE  500000
#define TOTAL_NODES (B * NNODE)

// fp32 node/decode tiles (proven R7 config)
#define MPB 32
#define DPB 16
#define RS  36
#define HS_RS (HID + 4)

// edge tensor kernel: 64 edges x 2 batches = 128 M-rows per block
#define KS1  264     // A1/B1 row stride (bf16): 128 hi + 128 lo + 8 pad
#define KS2  520     // A2/B2 row stride (bf16): 256 hi + 256 lo + 8 pad
#define DHS  68      // Dh row stride (f32)
// dynamic smem offsets (bytes)
#define OFF_A1  0        // 128*264*2 = 67584
#define OFF_B1  67584    // 256*264*2 = 135168 -> ends 202752
#define OFF_A2  0        // 128*520*2 = 133120 (overlays A1+B1 after GEMM1)
#define OFF_B2  133120   // 64*520*2  = 66560  -> ends 199680
#define OFF_DH  199680   // 64*68*4   = 17408  -> ends 217088
#define EDGE_DSMEM 217088

// ---------------------------------------------------------------------------
// device globals (allocation-guard-safe)
// ---------------------------------------------------------------------------
__device__ float g_H[(size_t)B * NNODE * OUT];
__device__ int   g_eu[NEDGE];
__device__ int   g_ev[NEDGE];
__device__ int   g_is64;
// pre-split, pre-transposed bf16 weight images [n][k']:
__device__ __align__(16) __nv_bfloat16 g_B1bf[256 * KS1]; // ew1: hi at k, lo at 128+k
__device__ __align__(16) __nv_bfloat16 g_B2bf[128 * KS2]; // ew2: hi at k, lo at 256+k

// ---------------------------------------------------------------------------
// helpers
// ---------------------------------------------------------------------------
static __device__ __forceinline__ void mma16816(float* d, const uint32_t* a, const uint32_t* b)
{
    asm volatile(
        "mma.sync.aligned.m16n8k16.row.col.f32.bf16.bf16.f32 "
        "{%0,%1,%2,%3}, {%4,%5,%6,%7}, {%8,%9}, {%0,%1,%2,%3};"
        : "+f"(d[0]), "+f"(d[1]), "+f"(d[2]), "+f"(d[3])
        : "r"(a[0]), "r"(a[1]), "r"(a[2]), "r"(a[3]), "r"(b[0]), "r"(b[1]));
}

static __device__ __forceinline__ void ldsm4(uint32_t& r0, uint32_t& r1, uint32_t& r2,
                                             uint32_t& r3, uint32_t addr)
{
    asm volatile("ldmatrix.sync.aligned.m8n8.x4.shared.b16 {%0,%1,%2,%3}, [%4];"
                 : "=r"(r0), "=r"(r1), "=r"(r2), "=r"(r3) : "r"(addr));
}

static __device__ __forceinline__ void cp16(uint32_t dst, const void* src)
{
    asm volatile("cp.async.cg.shared.global [%0], [%1], 16;" :: "r"(dst), "l"(src) : "memory");
}
#define CP_COMMIT() asm volatile("cp.async.commit_group;" ::: "memory")
#define CP_WAIT0()  asm volatile("cp.async.wait_group 0;" ::: "memory")

static __device__ __forceinline__ void red_add_v4(float* p, float a, float b, float c, float d)
{
    asm volatile("red.global.add.v4.f32 [%0], {%1, %2, %3, %4};"
                 :: "l"(p), "f"(a), "f"(b), "f"(c), "f"(d) : "memory");
}

static __device__ __forceinline__ void split_store(__nv_bfloat16* hi_p, __nv_bfloat16* lo_p,
                                                   float v0, float v1)
{
    __nv_bfloat162 hp = __floats2bfloat162_rn(v0, v1);
    const float h0 = __bfloat162float(hp.x), h1 = __bfloat162float(hp.y);
    __nv_bfloat162 lp = __floats2bfloat162_rn(v0 - h0, v1 - h1);
    *(uint32_t*)hi_p = *(const uint32_t*)&hp;
    *(uint32_t*)lo_p = *(const uint32_t*)&lp;
}

// ---------------------------------------------------------------------------
// edge dtype detect + SoA normalize (proven)
// ---------------------------------------------------------------------------
__global__ void detect_edge_dtype_kernel(const int* __restrict__ e32)
{
    if (threadIdx.x == 0 && blockIdx.x == 0) {
        int all_zero = 1;
        #pragma unroll 1
        for (int i = 1; i < 256; i += 2)
            if (e32[i] != 0) { all_zero = 0; break; }
        g_is64 = all_zero;
    }
}

__global__ __launch_bounds__(256) void convert_edges_kernel(const int* __restrict__ e32)
{
    const int e = blockIdx.x * 256 + threadIdx.x;
    if (e < NEDGE) {
        if (g_is64) { g_eu[e] = e32[4 * e + 0]; g_ev[e] = e32[4 * e + 2]; }
        else        { g_eu[e] = e32[2 * e + 0]; g_ev[e] = e32[2 * e + 1]; }
    }
}

// ---------------------------------------------------------------------------
// weight prep: split fp32 -> bf16 hi/lo, transpose to [n][k]
// ---------------------------------------------------------------------------
__global__ __launch_bounds__(256) void prep_weights_kernel(
    const float* __restrict__ ew1, const float* __restrict__ ew2)
{
    const int tid = blockIdx.x * 256 + threadIdx.x;
    const int stride = gridDim.x * 256;
    for (int idx = tid; idx < 256 * 128; idx += stride) {
        const int n = idx >> 7, k = idx & 127;
        const float w = ew1[k * HID + n];
        const __nv_bfloat16 hi = __float2bfloat16_rn(w);
        g_B1bf[n * KS1 + k]       = hi;
        g_B1bf[n * KS1 + 128 + k] = __float2bfloat16_rn(w - __bfloat162float(hi));
    }
    for (int idx = tid; idx < 128 * 256; idx += stride) {
        const int n = idx >> 8, k = idx & 255;
        const float w = ew2[k * OUT + n];
        const __nv_bfloat16 hi = __float2bfloat16_rn(w);
        g_B2bf[n * KS2 + k]       = hi;
        g_B2bf[n * KS2 + 256 + k] = __float2bfloat16_rn(w - __bfloat162float(hi));
    }
}

// ---------------------------------------------------------------------------
// Edge MLP v8: fused-batch split-bf16 mma.sync + ldmatrix + cp.async overlap
// ---------------------------------------------------------------------------
__global__ __launch_bounds__(256, 1) void edge_mlp_tc_kernel(
    const float* __restrict__ x,
    const float* __restrict__ eb1, const float* __restrict__ eb2)
{
    extern __shared__ __align__(16) char smc[];
    __nv_bfloat16* A1 = (__nv_bfloat16*)(smc + OFF_A1);
    __nv_bfloat16* B1 = (__nv_bfloat16*)(smc + OFF_B1);
    __nv_bfloat16* A2 = (__nv_bfloat16*)(smc + OFF_A2);
    float*         Dh = (float*)(smc + OFF_DH);

    __shared__ int   us[64], vs[64];
    __shared__ float eb1f[HID], eb2f[OUT];

    const int t   = threadIdx.x;
    const int wid = t >> 5;
    const int lid = t & 31;
    const int g   = lid >> 2;
    const int tg  = lid & 3;
    const int lr  = lid & 7;          // ldmatrix lane row
    const int lq  = (lid >> 3) & 1;   // ldmatrix quad bit
    const int lh  = lid >> 4;         // ldmatrix half bit
    const int e0  = blockIdx.x * 64;
    const int count = min(64, NEDGE - e0);

    const uint32_t sA1 = (uint32_t)__cvta_generic_to_shared(A1);
    const uint32_t sB1 = (uint32_t)__cvta_generic_to_shared(B1);
    const uint32_t sA2 = (uint32_t)__cvta_generic_to_shared(A2);
    const uint32_t sB2 = (uint32_t)__cvta_generic_to_shared(smc + OFF_B2);

    if (t < 64) {
        const int e = min(e0 + t, NEDGE - 1);
        us[t] = g_eu[e]; vs[t] = g_ev[e];
    }
    eb1f[t] = eb1[t];
    if (t < OUT) eb2f[t] = eb2[t];

    // prefetch B1 (all 256 n-rows, 135168 B) via cp.async — overlaps gather
    {
        const float4* src = (const float4*)g_B1bf;
        #pragma unroll 1
        for (int i = t; i < 8448; i += 256)
            cp16(sB1 + i * 16, src + i);
        CP_COMMIT();
    }
    __syncthreads();   // us/vs visible for gather

    // gather: rows 0-63 batch0, 64-127 batch1; split hi|lo into A1
    #pragma unroll
    for (int it = 0; it < 32; it++) {
        const int q = t + it * 256;                   // 8192 float2
        const int m = q >> 6;
        const int c = (q & 63) * 2;
        const int node = (c < IN_DIM) ? us[m & 63] : vs[m & 63];
        const float2 xv = *(const float2*)
            &x[((size_t)(m >> 6) * NNODE + node) * IN_DIM + (c & (IN_DIM - 1))];
        split_store(A1 + m * KS1 + c, A1 + m * KS1 + 128 + c, xv.x, xv.y);
    }
    CP_WAIT0();
    __syncthreads();

    // ---- GEMM1: warp tile 64m x 32n, both 128-n halves (ldmatrix frags) ----
    const int m1 = (wid >> 2) * 64;
    const int n1 = (wid & 3) * 32;
    uint32_t aAddr1[4], bAddr1[4];
    #pragma unroll
    for (int mi = 0; mi < 4; mi++)
        aAddr1[mi] = sA1 + ((m1 + mi * 16 + lr + lq * 8) * KS1 + lh * 8) * 2;
    #pragma unroll
    for (int h = 0; h < 2; h++)
        #pragma unroll
        for (int grp = 0; grp < 2; grp++)
            bAddr1[h * 2 + grp] = sB1 + ((h * 128 + n1 + grp * 16 + lh * 8 + lr) * KS1 + lq * 8) * 2;

    float acc1[2][4][4][4] = {};
    #pragma unroll 1
    for (int seg = 0; seg < 3; seg++) {
        const int aofs = ((seg == 1) ? 128 : 0) * 2;
        const int bofs = ((seg == 2) ? 128 : 0) * 2;
        #pragma unroll 2
        for (int k16 = 0; k16 < 8; k16++) {
            const int ka = aofs + k16 * 32;
            const int kb = bofs + k16 * 32;
            uint32_t a[4][4], bb[4][4];
            #pragma unroll
            for (int mi = 0; mi < 4; mi++)
                ldsm4(a[mi][0], a[mi][1], a[mi][2], a[mi][3], aAddr1[mi] + ka);
            #pragma unroll
            for (int j = 0; j < 4; j++)
                ldsm4(bb[j][0], bb[j][1], bb[j][2], bb[j][3], bAddr1[j] + kb);
            #pragma unroll
            for (int h = 0; h < 2; h++)
                #pragma unroll
                for (int nt = 0; nt < 4; nt++) {
                    const uint32_t* bp = (nt & 1) ? &bb[h * 2 + (nt >> 1)][2]
                                                  : &bb[h * 2 + (nt >> 1)][0];
                    #pragma unroll
                    for (int mi = 0; mi < 4; mi++)
                        mma16816(acc1[h][mi][nt], a[mi], bp);
                }
        }
    }
    __syncthreads();   // all GEMM1 reads done; A2 overlays A1 + B1[rows<124]

    // prefetch B2 half 0 (66560 B into [133120,199680) = B1 rows>=124, dead now)
    {
        const float4* src = (const float4*)g_B2bf;
        #pragma unroll 1
        for (int i = t; i < 4160; i += 256)
            cp16(sB2 + i * 16, src + i);
        CP_COMMIT();
    }

    // epilogue G1: bias + relu + split -> A2 [128m][256hi|256lo] (overlaps cp.async)
    #pragma unroll
    for (int h = 0; h < 2; h++) {
        #pragma unroll
        for (int mi = 0; mi < 4; mi++) {
            const int r0 = m1 + mi * 16 + g;
            #pragma unroll
            for (int nt = 0; nt < 4; nt++) {
                const int c = h * 128 + n1 + nt * 8 + tg * 2;
                const float b0 = eb1f[c], b1 = eb1f[c + 1];
                const float v0 = fmaxf(acc1[h][mi][nt][0] + b0, 0.f);
                const float v1 = fmaxf(acc1[h][mi][nt][1] + b1, 0.f);
                const float v2 = fmaxf(acc1[h][mi][nt][2] + b0, 0.f);
                const float v3 = fmaxf(acc1[h][mi][nt][3] + b1, 0.f);
                __nv_bfloat16* r0p = A2 + (size_t)r0 * KS2;
                __nv_bfloat16* r1p = A2 + (size_t)(r0 + 8) * KS2;
                split_store(r0p + c, r0p + 256 + c, v0, v1);
                split_store(r1p + c, r1p + 256 + c, v2, v3);
            }
        }
    }
    CP_WAIT0();
    __syncthreads();

    // ---- GEMM2: two 64-n halves; warp tile 32m x 32n (ldmatrix frags) ----
    const int m2 = (wid >> 1) * 32;
    const int n2 = (wid & 1) * 32;
    uint32_t aAddr2[2], bAddr2[2];
    #pragma unroll
    for (int mi = 0; mi < 2; mi++)
        aAddr2[mi] = sA2 + ((m2 + mi * 16 + lr + lq * 8) * KS2 + lh * 8) * 2;
    #pragma unroll
    for (int grp = 0; grp < 2; grp++)
        bAddr2[grp] = sB2 + ((n2 + grp * 16 + lh * 8 + lr) * KS2 + lq * 8) * 2;

    #pragma unroll 1
    for (int h2 = 0; h2 < 2; h2++) {
        float acc2[2][4][4] = {};
        #pragma unroll 1
        for (int seg = 0; seg < 3; seg++) {
            const int aofs = ((seg == 1) ? 256 : 0) * 2;
            const int bofs = ((seg == 2) ? 256 : 0) * 2;
            #pragma unroll 2
            for (int k16 = 0; k16 < 16; k16++) {
                const int ka = aofs + k16 * 32;
                const int kb = bofs + k16 * 32;
                uint32_t a[2][4], bb[2][4];
                #pragma unroll
                for (int mi = 0; mi < 2; mi++)
                    ldsm4(a[mi][0], a[mi][1], a[mi][2], a[mi][3], aAddr2[mi] + ka);
                #pragma unroll
                for (int j = 0; j < 2; j++)
                    ldsm4(bb[j][0], bb[j][1], bb[j][2], bb[j][3], bAddr2[j] + kb);
                #pragma unroll
                for (int nt = 0; nt < 4; nt++) {
                    const uint32_t* bp = (nt & 1) ? &bb[nt >> 1][2] : &bb[nt >> 1][0];
                    mma16816(acc2[0][nt], a[0], bp);
                    mma16816(acc2[1][nt], a[1], bp);
                }
            }
        }
        __syncthreads();   // GEMM2 half reads done; B2 buffer reusable

        if (h2 == 0) {     // prefetch B2 half 1 — overlaps scatter of half 0
            const float4* src = (const float4*)(g_B2bf + (size_t)64 * KS2);
            #pragma unroll 1
            for (int i = t; i < 4160; i += 256)
                cp16(sB2 + i * 16, src + i);
            CP_COMMIT();
        }

        // scatter in 2 phases of 64 m-rows (phase pg == batch pg)
        #pragma unroll 1
        for (int pg = 0; pg < 2; pg++) {
            if ((wid >> 1) == pg * 2 || (wid >> 1) == pg * 2 + 1) { /* warps with m2 in phase */ }
            if (m2 >> 6 == pg) {     // warps owning m in [pg*64, pg*64+64)
                #pragma unroll
                for (int mi = 0; mi < 2; mi++) {
                    const int r = m2 + mi * 16 + g - pg * 64;
                    #pragma unroll
                    for (int nt = 0; nt < 4; nt++) {
                        const int cc = n2 + nt * 8 + tg * 2;
                        const float b0 = eb2f[h2 * 64 + cc];
                        const float b1 = eb2f[h2 * 64 + cc + 1];
                        float2 lo, hi;
                        lo.x = acc2[mi][nt][0] + b0;
                        lo.y = acc2[mi][nt][1] + b1;
                        hi.x = acc2[mi][nt][2] + b0;
                        hi.y = acc2[mi][nt][3] + b1;
                        *(float2*)&Dh[r * DHS + cc]       = lo;
                        *(float2*)&Dh[(r + 8) * DHS + cc] = hi;
                    }
                }
            }
            __syncthreads();
            float* Hb = g_H + (size_t)pg * NNODE * OUT;
            #pragma unroll 1
            for (int i = t; i < 1024; i += 256) {
                const int r  = i >> 4;
                const int c4 = (i & 15) * 4;
                if (r < count) {
                    const float4 vv = *(const float4*)&Dh[r * DHS + c4];
                    red_add_v4(&Hb[(size_t)us[r] * OUT + h2 * 64 + c4], vv.x, vv.y, vv.z, vv.w);
                    red_add_v4(&Hb[(size_t)vs[r] * OUT + h2 * 64 + c4], vv.x, vv.y, vv.z, vv.w);
                }
            }
            __syncthreads();
        }
        if (h2 == 0) { CP_WAIT0(); __syncthreads(); }
    }
}

// ---------------------------------------------------------------------------
// Node MLP (fp32, R7 proven)
// ---------------------------------------------------------------------------
__global__ __launch_bounds__(256, 3) void node_mlp_kernel(
    const float* __restrict__ x,
    const float* __restrict__ nw1, const float* __restrict__ nb1,
    const float* __restrict__ nw2, const float* __restrict__ nb2)
{
    extern __shared__ float sm[];
    float* xsT = sm;
    float* hs  = sm + IN_DIM * RS;
    float* ws  = hs + MPB * HS_RS;

    const int t    = threadIdx.x;
    const int base = blockIdx.x * MPB;

    #pragma unroll
    for (int i = 0; i < 2; i++) {
        const int q  = t + i * 256;
        const int m  = q >> 4;
        const int c4 = (q & 15) * 4;
        const float4 v = *(const float4*)&x[(size_t)(base + m) * IN_DIM + c4];
        xsT[(c4 + 0) * RS + m] = v.x;
        xsT[(c4 + 1) * RS + m] = v.y;
        xsT[(c4 + 2) * RS + m] = v.z;
        xsT[(c4 + 3) * RS + m] = v.w;
    }

    {
        const int m0 = (t >> 6) * 8;
        const int n0 = (t & 63) * 4;
        const float4 b1 = *(const float4*)&nb1[n0];
        float acc[8][4];
        #pragma unroll
        for (int i = 0; i < 8; i++) {
            acc[i][0] = b1.x; acc[i][1] = b1.y; acc[i][2] = b1.z; acc[i][3] = b1.w;
        }
        #pragma unroll 1
        for (int kc = 0; kc < IN_DIM / 16; kc++) {
            __syncthreads();
            {
                const float4* src = (const float4*)(nw1 + kc * 16 * HID);
                float4* dst = (float4*)ws;
                #pragma unroll
                for (int j = 0; j < 4; j++) dst[t + j * 256] = src[t + j * 256];
            }
            __syncthreads();
            const float* aT = xsT + kc * 16 * RS;
            #pragma unroll 4
            for (int k = 0; k < 16; k++) {
                const float4 bv = *(const float4*)&ws[k * HID + n0];
                const float4 a0 = *(const float4*)&aT[k * RS + m0];
                const float4 a1 = *(const float4*)&aT[k * RS + m0 + 4];
                acc[0][0] = fmaf(a0.x, bv.x, acc[0][0]); acc[0][1] = fmaf(a0.x, bv.y, acc[0][1]);
                acc[0][2] = fmaf(a0.x, bv.z, acc[0][2]); acc[0][3] = fmaf(a0.x, bv.w, acc[0][3]);
                acc[1][0] = fmaf(a0.y, bv.x, acc[1][0]); acc[1][1] = fmaf(a0.y, bv.y, acc[1][1]);
                acc[1][2] = fmaf(a0.y, bv.z, acc[1][2]); acc[1][3] = fmaf(a0.y, bv.w, acc[1][3]);
                acc[2][0] = fmaf(a0.z, bv.x, acc[2][0]); acc[2][1] = fmaf(a0.z, bv.y, acc[2][1]);
                acc[2][2] = fmaf(a0.z, bv.z, acc[2][2]); acc[2][3] = fmaf(a0.z, bv.w, acc[2][3]);
                acc[3][0] = fmaf(a0.w, bv.x, acc[3][0]); acc[3][1] = fmaf(a0.w, bv.y, acc[3][1]);
                acc[3][2] = fmaf(a0.w, bv.z, acc[3][2]); acc[3][3] = fmaf(a0.w, bv.w, acc[3][3]);
                acc[4][0] = fmaf(a1.x, bv.x, acc[4][0]); acc[4][1] = fmaf(a1.x, bv.y, acc[4][1]);
                acc[4][2] = fmaf(a1.x, bv.z, acc[4][2]); acc[4][3] = fmaf(a1.x, bv.w, acc[4][3]);
                acc[5][0] = fmaf(a1.y, bv.x, acc[5][0]); acc[5][1] = fmaf(a1.y, bv.y, acc[5][1]);
                acc[5][2] = fmaf(a1.y, bv.z, acc[5][2]); acc[5][3] = fmaf(a1.y, bv.w, acc[5][3]);
                acc[6][0] = fmaf(a1.z, bv.x, acc[6][0]); acc[6][1] = fmaf(a1.z, bv.y, acc[6][1]);
                acc[6][2] = fmaf(a1.z, bv.z, acc[6][2]); acc[6][3] = fmaf(a1.z, bv.w, acc[6][3]);
                acc[7][0] = fmaf(a1.w, bv.x, acc[7][0]); acc[7][1] = fmaf(a1.w, bv.y, acc[7][1]);
                acc[7][2] = fmaf(a1.w, bv.z, acc[7][2]); acc[7][3] = fmaf(a1.w, bv.w, acc[7][3]);
            }
        }
        #pragma unroll
        for (int i = 0; i < 8; i++) {
            float4 r = make_float4(fmaxf(acc[i][0], 0.f), fmaxf(acc[i][1], 0.f),
                                   fmaxf(acc[i][2], 0.f), fmaxf(acc[i][3], 0.f));
            *(float4*)&hs[(m0 + i) * HS_RS + n0] = r;
        }
    }

    {
        const int m0 = (t >> 5) * 4;
        const int n0 = (t & 31) * 4;
        const float4 b2 = *(const float4*)&nb2[n0];
        float acc[4][4];
        #pragma unroll
        for (int i = 0; i < 4; i++) {
            acc[i][0] = b2.x; acc[i][1] = b2.y; acc[i][2] = b2.z; acc[i][3] = b2.w;
        }
        #pragma unroll 1
        for (int kc = 0; kc < HID / 32; kc++) {
            __syncthreads();
            {
                const float4* src = (const float4*)(nw2 + kc * 32 * OUT);
                float4* dst = (float4*)ws;
                #pragma unroll
                for (int j = 0; j < 4; j++) dst[t + j * 256] = src[t + j * 256];
            }
            __syncthreads();
            #pragma unroll 2
            for (int k4 = 0; k4 < 32; k4 += 4) {
                const float4 b0  = *(const float4*)&ws[(k4 + 0) * OUT + n0];
                const float4 b1v = *(const float4*)&ws[(k4 + 1) * OUT + n0];
                const float4 b2v = *(const float4*)&ws[(k4 + 2) * OUT + n0];
                const float4 b3v = *(const float4*)&ws[(k4 + 3) * OUT + n0];
                #pragma unroll
                for (int i = 0; i < 4; i++) {
                    const float4 a = *(const float4*)&hs[(m0 + i) * HS_RS + kc * 32 + k4];
                    acc[i][0] = fmaf(a.x, b0.x,  acc[i][0]);
                    acc[i][1] = fmaf(a.x, b0.y,  acc[i][1]);
                    acc[i][2] = fmaf(a.x, b0.z,  acc[i][2]);
                    acc[i][3] = fmaf(a.x, b0.w,  acc[i][3]);
                    acc[i][0] = fmaf(a.y, b1v.x, acc[i][0]);
                    acc[i][1] = fmaf(a.y, b1v.y, acc[i][1]);
                    acc[i][2] = fmaf(a.y, b1v.z, acc[i][2]);
                    acc[i][3] = fmaf(a.y, b1v.w, acc[i][3]);
                    acc[i][0] = fmaf(a.z, b2v.x, acc[i][0]);
                    acc[i][1] = fmaf(a.z, b2v.y, acc[i][1]);
                    acc[i][2] = fmaf(a.z, b2v.z, acc[i][2]);
                    acc[i][3] = fmaf(a.z, b2v.w, acc[i][3]);
                    acc[i][0] = fmaf(a.w, b3v.x, acc[i][0]);
                    acc[i][1] = fmaf(a.w, b3v.y, acc[i][1]);
                    acc[i][2] = fmaf(a.w, b3v.z, acc[i][2]);
                    acc[i][3] = fmaf(a.w, b3v.w, acc[i][3]);
                }
            }
        }
        #pragma unroll
        for (int i = 0; i < 4; i++)
            *(float4*)&g_H[(size_t)(base + m0 + i) * OUT + n0] =
                make_float4(acc[i][0], acc[i][1], acc[i][2], acc[i][3]);
    }
}

// ---------------------------------------------------------------------------
// decode: out = H @ dw + db (unchanged)
// ---------------------------------------------------------------------------
__global__ __launch_bounds__(256) void decode_kernel(
    const float* __restrict__ dw, const float* __restrict__ db,
    float* __restrict__ out)
{
    __shared__ __align__(16) float hsm[DPB][OUT];

    const int base = blockIdx.x * DPB;
    const int t = threadIdx.x;

    for (int i = t; i < DPB * OUT; i += 256)
        hsm[i / OUT][i % OUT] = g_H[(size_t)base * OUT + i];
    __syncthreads();

    const int o   = t & (IN_DIM - 1);
    const int nb0 = (t >> 6) * (DPB / 4);
    float acc[DPB / 4];
    {
        const float bb = db[o];
        #pragma unroll
        for (int n = 0; n < DPB / 4; n++) acc[n] = bb;
    }
    #pragma unroll 4
    for (int k = 0; k < OUT; k += 4) {
        const float w0 = dw[(k + 0) * IN_DIM + o];
        const float w1 = dw[(k + 1) * IN_DIM + o];
        const float w2 = dw[(k + 2) * IN_DIM + o];
        const float w3 = dw[(k + 3) * IN_DIM + o];
        #pragma unroll
        for (int n = 0; n < DPB / 4; n++) {
            float4 v = *reinterpret_cast<const float4*>(&hsm[nb0 + n][k]);
            acc[n] = fmaf(v.x, w0, acc[n]);
            acc[n] = fmaf(v.y, w1, acc[n]);
            acc[n] = fmaf(v.z, w2, acc[n]);
            acc[n] = fmaf(v.w, w3, acc[n]);
        }
    }
    #pragma unroll
    for (int n = 0; n < DPB / 4; n++)
        out[(size_t)(base + nb0 + n) * IN_DIM + o] = acc[n];
}

// ---------------------------------------------------------------------------
extern "C" void kernel_launch(void* const* d_in, const int* in_sizes, int n_in,
                              void* d_out, int out_size)
{
    const float* x   = (const float*)d_in[0];
    const int*   e32 = (const int*)d_in[1];
    const float* ew1 = (const float*)d_in[2];
    const float* eb1 = (const float*)d_in[3];
    const float* ew2 = (const float*)d_in[4];
    const float* eb2 = (const float*)d_in[5];
    const float* nw1 = (const float*)d_in[6];
    const float* nb1 = (const float*)d_in[7];
    const float* nw2 = (const float*)d_in[8];
    const float* nb2 = (const float*)d_in[9];
    const float* dw  = (const float*)d_in[10];
    const float* db  = (const float*)d_in[11];
    float*       out = (float*)d_out;

    const int node_smem = (IN_DIM * RS + MPB * HS_RS + 16 * HID) * (int)sizeof(float); // 58880

    static bool attr_done = false;
    if (!attr_done) {
        cudaFuncSetAttribute(edge_mlp_tc_kernel,
            cudaFuncAttributeMaxDynamicSharedMemorySize, EDGE_DSMEM);
        cudaFuncSetAttribute(node_mlp_kernel,
            cudaFuncAttributeMaxDynamicSharedMemorySize, node_smem);
        attr_done = true;
    }

    detect_edge_dtype_kernel<<<1, 32>>>(e32);
    convert_edges_kernel<<<(NEDGE + 255) / 256, 256>>>(e32);
    prep_weights_kernel<<<128, 256>>>(ew1, ew2);

    node_mlp_kernel<<<TOTAL_NODES / MPB, 256, node_smem>>>(x, nw1, nb1, nw2, nb2);

    edge_mlp_tc_kernel<<<(NEDGE + 63) / 64, 256, EDGE_DSMEM>>>(x, eb1, eb2);

    decode_kernel<<<TOTAL_NODES / DPB, 256>>>(dw, db, out);
}